// round 14
// baseline (speedup 1.0000x reference)
#include <cuda_runtime.h>
#include <cuda_bf16.h>
#include <cuda_fp16.h>
#include <math_constants.h>
#include <cstdint>

// Shapes (fixed)
#define BB 8
#define LL 1024
#define HH 512
#define FF 4
#define HF 2048
#define H2 1024
#define MROWS 8192

// ---------------- scratch (device globals) ----------------------------------
// 8 score streams: q = f*2 + khalf  (K split at 256)
__device__ __align__(256) float g_Sf[(size_t)2 * FF * BB * LL * LL];
__device__ __align__(256) float g_joint[(size_t)MROWS * H2];
__device__ __align__(256) __nv_bfloat16 g_jh[(size_t)MROWS * H2];
__device__ __align__(256) __nv_bfloat16 g_jl[(size_t)MROWS * H2];
__device__ __align__(256) __half g_j16[(size_t)MROWS * H2];
__device__ __align__(256) __half g_xt16[(size_t)BB * HH * LL];
__device__ __align__(256) __nv_bfloat16 g_wph[(size_t)HF * HH];
__device__ __align__(256) __nv_bfloat16 g_wpl[(size_t)HF * HH];
__device__ __align__(256) float g_bpr[HF];
__device__ __align__(256) __half g_wg16[(size_t)H2 * H2];
__device__ __align__(256) __nv_bfloat16 g_yh[(size_t)BB * FF * LL * HH];
__device__ __align__(256) __nv_bfloat16 g_yl[(size_t)BB * FF * LL * HH];
__device__ __align__(256) __half g_ah16[(size_t)BB * LL * LL];
__device__ __align__(256) __half g_al16[(size_t)BB * LL * LL];
// compaction
__device__ int g_idx[BB][LL];
__device__ int g_midx[BB][LL];
__device__ int g_cpos[BB * LL];
__device__ int g_cnt[BB];

// ---------------- helpers ----------------------------------------------------
__device__ __forceinline__ void split2(float v, __nv_bfloat16& h, __nv_bfloat16& l) {
    h = __float2bfloat16_rn(v);
    l = __float2bfloat16_rn(v - __bfloat162float(h));
}
__device__ __forceinline__ void split2h(float v, __half& h, __half& l) {
    h = __float2half_rn(v);
    l = __float2half_rn(v - __half2float(h));
}
__device__ __forceinline__ void cp16(void* smem, const void* gmem) {
    unsigned s = (unsigned)__cvta_generic_to_shared(smem);
    asm volatile("cp.async.cg.shared.global [%0], [%1], 16;\n" :: "r"(s), "l"(gmem));
}
__device__ __forceinline__ void cp_commit() { asm volatile("cp.async.commit_group;\n"); }
__device__ __forceinline__ void cp_wait0()  { asm volatile("cp.async.wait_group 0;\n"); }
__device__ __forceinline__ void cp_wait1()  { asm volatile("cp.async.wait_group 1;\n"); }

__device__ __forceinline__ void ldsm4(unsigned& r0, unsigned& r1, unsigned& r2, unsigned& r3,
                                      const void* p) {
    unsigned s = (unsigned)__cvta_generic_to_shared(p);
    asm volatile("ldmatrix.sync.aligned.m8n8.x4.shared.b16 {%0,%1,%2,%3}, [%4];\n"
                 : "=r"(r0), "=r"(r1), "=r"(r2), "=r"(r3) : "r"(s));
}
__device__ __forceinline__ void mma16816(float* c, const unsigned* a, const unsigned* b) {
    asm volatile(
        "mma.sync.aligned.m16n8k16.row.col.f32.bf16.bf16.f32 "
        "{%0,%1,%2,%3}, {%4,%5,%6,%7}, {%8,%9}, {%0,%1,%2,%3};\n"
        : "+f"(c[0]), "+f"(c[1]), "+f"(c[2]), "+f"(c[3])
        : "r"(a[0]), "r"(a[1]), "r"(a[2]), "r"(a[3]), "r"(b[0]), "r"(b[1]));
}
__device__ __forceinline__ void mma16816h(float* c, const unsigned* a, const unsigned* b) {
    asm volatile(
        "mma.sync.aligned.m16n8k16.row.col.f32.f16.f16.f32 "
        "{%0,%1,%2,%3}, {%4,%5,%6,%7}, {%8,%9}, {%0,%1,%2,%3};\n"
        : "+f"(c[0]), "+f"(c[1]), "+f"(c[2]), "+f"(c[3])
        : "r"(a[0]), "r"(a[1]), "r"(a[2]), "r"(a[3]), "r"(b[0]), "r"(b[1]));
}

// ---------------- shared tile geometry ----------------------------------------
#define BM 128
#define BN 128
#define BK 32
#define SSTR 40
#define TILE_E (128 * SSTR)

// ============ 3-term bf16 template (proj, scores): 4 tiles, 2 stages ==========
#define STAGE_E (4 * TILE_E)
#define SMEM_BYTES (2 * STAGE_E * 2)

__device__ __forceinline__ void load_stage(__nv_bfloat16* st,
                                           const __nv_bfloat16* Ah, const __nv_bfloat16* Al,
                                           const int* __restrict__ rowoff,
                                           const __nv_bfloat16* Bh, const __nv_bfloat16* Bl, int ldb,
                                           int n0, int kk, int tid) {
    __nv_bfloat16* sAH = st;
    __nv_bfloat16* sAL = st + TILE_E;
    __nv_bfloat16* sBH = st + 2 * TILE_E;
    __nv_bfloat16* sBL = st + 3 * TILE_E;
#pragma unroll
    for (int i = 0; i < 2; ++i) {
        int q = tid + i * 256;
        int r = q >> 2, c = (q & 3) * 8;
        size_t ga = (size_t)rowoff[r] + kk + c;
        size_t gb = (size_t)(n0 + r) * ldb + kk + c;
        cp16(&sAH[r * SSTR + c], &Ah[ga]);
        cp16(&sAL[r * SSTR + c], &Al[ga]);
        cp16(&sBH[r * SSTR + c], &Bh[gb]);
        cp16(&sBL[r * SSTR + c], &Bl[gb]);
    }
    cp_commit();
}

__device__ __forceinline__ void compute_stage(float (&acc)[4][4][4],
                                              const __nv_bfloat16* st,
                                              int wm, int wn, int lane) {
    const __nv_bfloat16* sAH = st;
    const __nv_bfloat16* sAL = st + TILE_E;
    const __nv_bfloat16* sBH = st + 2 * TILE_E;
    const __nv_bfloat16* sBL = st + 3 * TILE_E;
#pragma unroll
    for (int ks = 0; ks < 2; ++ks) {
        const int col = ks * 16 + (lane >> 4) * 8;
        const int arow = wm * 64 + (lane & 15);
        const int brow = wn * 32 + (lane & 15);
        unsigned ah[4][4], al[4][4], bh[4][2], bl[4][2];
#pragma unroll
        for (int mt = 0; mt < 4; ++mt) {
            ldsm4(ah[mt][0], ah[mt][1], ah[mt][2], ah[mt][3], &sAH[(arow + mt * 16) * SSTR + col]);
            ldsm4(al[mt][0], al[mt][1], al[mt][2], al[mt][3], &sAL[(arow + mt * 16) * SSTR + col]);
        }
#pragma unroll
        for (int np = 0; np < 2; ++np) {
            unsigned r0, r1, r2, r3;
            ldsm4(r0, r1, r2, r3, &sBH[(brow + np * 16) * SSTR + col]);
            bh[np * 2 + 0][0] = r0; bh[np * 2 + 1][0] = r1;
            bh[np * 2 + 0][1] = r2; bh[np * 2 + 1][1] = r3;
            ldsm4(r0, r1, r2, r3, &sBL[(brow + np * 16) * SSTR + col]);
            bl[np * 2 + 0][0] = r0; bl[np * 2 + 1][0] = r1;
            bl[np * 2 + 0][1] = r2; bl[np * 2 + 1][1] = r3;
        }
#pragma unroll
        for (int mt = 0; mt < 4; ++mt)
#pragma unroll
            for (int nt = 0; nt < 4; ++nt)
                mma16816(acc[mt][nt], ah[mt], bh[nt]);
#pragma unroll
        for (int mt = 0; mt < 4; ++mt)
#pragma unroll
            for (int nt = 0; nt < 4; ++nt)
                mma16816(acc[mt][nt], ah[mt], bl[nt]);
#pragma unroll
        for (int mt = 0; mt < 4; ++mt)
#pragma unroll
            for (int nt = 0; nt < 4; ++nt)
                mma16816(acc[mt][nt], al[mt], bh[nt]);
    }
}

__device__ __forceinline__ void gemm_main(float (&acc)[4][4][4], __nv_bfloat16* sm,
                                          const __nv_bfloat16* Ah, const __nv_bfloat16* Al,
                                          const int* __restrict__ rowoff,
                                          const __nv_bfloat16* Bh, const __nv_bfloat16* Bl, int ldb,
                                          int K, int n0) {
    const int tid = threadIdx.x;
    const int lane = tid & 31, warp = tid >> 5;
    const int wm = warp & 1, wn = warp >> 1;
    const int S = K / BK;

    load_stage(sm, Ah, Al, rowoff, Bh, Bl, ldb, n0, 0, tid);
    for (int s = 0; s < S; ++s) {
        cp_wait0();
        __syncthreads();
        if (s + 1 < S)
            load_stage(sm + ((s + 1) & 1) * STAGE_E, Ah, Al, rowoff, Bh, Bl, ldb,
                       n0, (s + 1) * BK, tid);
        compute_stage(acc, sm + (s & 1) * STAGE_E, wm, wn, lane);
    }
}

// ============ 2-term fp16 template (enc): 3 tiles, 3 stages ====================
#define STAGE2_E (3 * TILE_E)
#define SMEM2_BYTES (3 * STAGE2_E * 2)

__device__ __forceinline__ void load_stage2(__half* st,
                                            const __half* Ah, const __half* Al,
                                            const int* __restrict__ rowoff,
                                            const __half* B, int ldb,
                                            int n0, int kk, int tid) {
    __half* sAH = st;
    __half* sAL = st + TILE_E;
    __half* sB  = st + 2 * TILE_E;
#pragma unroll
    for (int i = 0; i < 2; ++i) {
        int q = tid + i * 256;
        int r = q >> 2, c = (q & 3) * 8;
        size_t ga = (size_t)rowoff[r] + kk + c;
        size_t gb = (size_t)(n0 + r) * ldb + kk + c;
        cp16(&sAH[r * SSTR + c], &Ah[ga]);
        cp16(&sAL[r * SSTR + c], &Al[ga]);
        cp16(&sB[r * SSTR + c], &B[gb]);
    }
    cp_commit();
}

__device__ __forceinline__ void compute_stage2(float (&acc)[4][4][4],
                                               const __half* st,
                                               int wm, int wn, int lane) {
    const __half* sAH = st;
    const __half* sAL = st + TILE_E;
    const __half* sB  = st + 2 * TILE_E;
#pragma unroll
    for (int ks = 0; ks < 2; ++ks) {
        const int col = ks * 16 + (lane >> 4) * 8;
        const int arow = wm * 64 + (lane & 15);
        const int brow = wn * 32 + (lane & 15);
        unsigned ah[4][4], al[4][4], bb[4][2];
#pragma unroll
        for (int mt = 0; mt < 4; ++mt) {
            ldsm4(ah[mt][0], ah[mt][1], ah[mt][2], ah[mt][3], &sAH[(arow + mt * 16) * SSTR + col]);
            ldsm4(al[mt][0], al[mt][1], al[mt][2], al[mt][3], &sAL[(arow + mt * 16) * SSTR + col]);
        }
#pragma unroll
        for (int np = 0; np < 2; ++np) {
            unsigned r0, r1, r2, r3;
            ldsm4(r0, r1, r2, r3, &sB[(brow + np * 16) * SSTR + col]);
            bb[np * 2 + 0][0] = r0; bb[np * 2 + 1][0] = r1;
            bb[np * 2 + 0][1] = r2; bb[np * 2 + 1][1] = r3;
        }
#pragma unroll
        for (int mt = 0; mt < 4; ++mt)
#pragma unroll
            for (int nt = 0; nt < 4; ++nt)
                mma16816h(acc[mt][nt], ah[mt], bb[nt]);
#pragma unroll
        for (int mt = 0; mt < 4; ++mt)
#pragma unroll
            for (int nt = 0; nt < 4; ++nt)
                mma16816h(acc[mt][nt], al[mt], bb[nt]);
    }
}

__device__ __forceinline__ void gemm2_main(float (&acc)[4][4][4], __half* sm,
                                           const __half* Ah, const __half* Al,
                                           const int* __restrict__ rowoff,
                                           const __half* B, int ldb,
                                           int K, int n0) {
    const int tid = threadIdx.x;
    const int lane = tid & 31, warp = tid >> 5;
    const int wm = warp & 1, wn = warp >> 1;
    const int S = K / BK;

    load_stage2(sm, Ah, Al, rowoff, B, ldb, n0, 0, tid);
    load_stage2(sm + STAGE2_E, Ah, Al, rowoff, B, ldb, n0, BK, tid);
    for (int s = 0; s < S; ++s) {
        if (s + 2 < S) cp_wait1(); else cp_wait0();
        __syncthreads();
        if (s + 2 < S)
            load_stage2(sm + (uint32_t)((s + 2) % 3) * STAGE2_E, Ah, Al, rowoff, B, ldb,
                        n0, (s + 2) * BK, tid);
        compute_stage2(acc, sm + (uint32_t)(s % 3) * STAGE2_E, wm, wn, lane);
    }
}

// ============ 1-term fp16 template (gate): 2 tiles, 3 stages ===================
#define STAGE1_E (2 * TILE_E)
#define SMEM1_BYTES (3 * STAGE1_E * 2)

__device__ __forceinline__ void load_stage1(__half* st,
                                            const __half* A,
                                            const int* __restrict__ rowoff,
                                            const __half* B, int ldb,
                                            int n0, int kk, int tid) {
    __half* sA = st;
    __half* sB = st + TILE_E;
#pragma unroll
    for (int i = 0; i < 2; ++i) {
        int q = tid + i * 256;
        int r = q >> 2, c = (q & 3) * 8;
        size_t ga = (size_t)rowoff[r] + kk + c;
        size_t gb = (size_t)(n0 + r) * ldb + kk + c;
        cp16(&sA[r * SSTR + c], &A[ga]);
        cp16(&sB[r * SSTR + c], &B[gb]);
    }
    cp_commit();
}

__device__ __forceinline__ void compute_stage1(float (&acc)[4][4][4],
                                               const __half* st,
                                               int wm, int wn, int lane) {
    const __half* sA = st;
    const __half* sB = st + TILE_E;
#pragma unroll
    for (int ks = 0; ks < 2; ++ks) {
        const int col = ks * 16 + (lane >> 4) * 8;
        const int arow = wm * 64 + (lane & 15);
        const int brow = wn * 32 + (lane & 15);
        unsigned aa[4][4], bb[4][2];
#pragma unroll
        for (int mt = 0; mt < 4; ++mt)
            ldsm4(aa[mt][0], aa[mt][1], aa[mt][2], aa[mt][3], &sA[(arow + mt * 16) * SSTR + col]);
#pragma unroll
        for (int np = 0; np < 2; ++np) {
            unsigned r0, r1, r2, r3;
            ldsm4(r0, r1, r2, r3, &sB[(brow + np * 16) * SSTR + col]);
            bb[np * 2 + 0][0] = r0; bb[np * 2 + 1][0] = r1;
            bb[np * 2 + 0][1] = r2; bb[np * 2 + 1][1] = r3;
        }
#pragma unroll
        for (int mt = 0; mt < 4; ++mt)
#pragma unroll
            for (int nt = 0; nt < 4; ++nt)
                mma16816h(acc[mt][nt], aa[mt], bb[nt]);
    }
}

__device__ __forceinline__ void gemm1_main(float (&acc)[4][4][4], __half* sm,
                                           const __half* A,
                                           const int* __restrict__ rowoff,
                                           const __half* B, int ldb,
                                           int K, int n0) {
    const int tid = threadIdx.x;
    const int lane = tid & 31, warp = tid >> 5;
    const int wm = warp & 1, wn = warp >> 1;
    const int S = K / BK;

    load_stage1(sm, A, rowoff, B, ldb, n0, 0, tid);
    load_stage1(sm + STAGE1_E, A, rowoff, B, ldb, n0, BK, tid);
    for (int s = 0; s < S; ++s) {
        if (s + 2 < S) cp_wait1(); else cp_wait0();
        __syncthreads();
        if (s + 2 < S)
            load_stage1(sm + (uint32_t)((s + 2) % 3) * STAGE1_E, A, rowoff, B, ldb,
                        n0, (s + 2) * BK, tid);
        compute_stage1(acc, sm + (uint32_t)(s % 3) * STAGE1_E, wm, wn, lane);
    }
}

// ---------------- compaction -----------------------------------------------
__global__ void k_compact(const int* __restrict__ xmask) {
    const int b = blockIdx.x;
    const int t = threadIdx.x;
    __shared__ int sc[1024];
    int m = xmask[b * LL + t];
    sc[t] = m;
    __syncthreads();
    for (int off = 1; off < 1024; off <<= 1) {
        int v = (t >= off) ? sc[t - off] : 0;
        __syncthreads();
        sc[t] += v;
        __syncthreads();
    }
    int pos = sc[t] - m;
    if (m) { g_idx[b][pos] = t; g_cpos[b * LL + t] = pos; }
    else   { g_midx[b][t - sc[t]] = t; g_cpos[b * LL + t] = -1; }
    int c = sc[1023];
    if (t == 0) g_cnt[b] = c;
    if (t >= c)      g_idx[b][t] = 0;
    if (t >= LL - c) g_midx[b][t] = 0;
}

// ---------------- prep kernels -----------------------------------------------
__global__ void k_prep_x(const float* __restrict__ X) {
    __shared__ float tile[32][33];
    const int b = blockIdx.z;
    const int l0 = blockIdx.y * 32, h0 = blockIdx.x * 32;
    const int tx = threadIdx.x, ty = threadIdx.y;
#pragma unroll
    for (int i = 0; i < 4; ++i) {
        int l = l0 + ty + 8 * i;
        float v = X[((size_t)b * LL + l) * HH + h0 + tx];
        tile[ty + 8 * i][tx] = v;
        size_t jo = ((size_t)b * LL + l) * H2 + h0 + tx;
        __nv_bfloat16 hh, ll; split2(v, hh, ll);
        g_jh[jo] = hh; g_jl[jo] = ll;
        g_j16[jo] = __float2half_rn(v);
    }
    __syncthreads();
#pragma unroll
    for (int i = 0; i < 4; ++i) {
        int h = h0 + ty + 8 * i;
        int l = l0 + tx;
        float v = tile[tx][ty + 8 * i];
        int p = g_cpos[b * LL + l];
        if (p >= 0)
            g_xt16[((size_t)b * HH + h) * LL + p] = __float2half_rn(v);
    }
}

__global__ void k_prep_wp(const float* __restrict__ W, const float* __restrict__ bp) {
    __shared__ float tile[32][33];
    const int k0 = blockIdx.y * 32, n0 = blockIdx.x * 32;
    const int tx = threadIdx.x, ty = threadIdx.y;
#pragma unroll
    for (int i = 0; i < 4; ++i)
        tile[ty + 8 * i][tx] = W[(size_t)(k0 + ty + 8 * i) * HF + n0 + tx];
    __syncthreads();
#pragma unroll
    for (int i = 0; i < 4; ++i) {
        int n = n0 + ty + 8 * i;
        int np = ((n & 3) << 9) + (n >> 2);
        float v = tile[tx][ty + 8 * i];
        __nv_bfloat16 hh, ll; split2(v, hh, ll);
        size_t o = (size_t)np * HH + k0 + tx;
        g_wph[o] = hh; g_wpl[o] = ll;
        if (k0 == 0 && tx == 0) g_bpr[np] = bp[n];
    }
}

__global__ void k_prep_wg(const float* __restrict__ W) {
    __shared__ float tile[32][33];
    const int k0 = blockIdx.y * 32, n0 = blockIdx.x * 32;
    const int tx = threadIdx.x, ty = threadIdx.y;
#pragma unroll
    for (int i = 0; i < 4; ++i)
        tile[ty + 8 * i][tx] = W[(size_t)(k0 + ty + 8 * i) * H2 + n0 + tx];
    __syncthreads();
#pragma unroll
    for (int i = 0; i < 4; ++i) {
        int n = n0 + ty + 8 * i;
        float v = tile[tx][ty + 8 * i];
        g_wg16[(size_t)n * H2 + k0 + tx] = __float2half_rn(32.0f * v);
    }
}

// ---------------- GEMM kernels -------------------------------------------------
// proj (compact rows)
__global__ __launch_bounds__(256, 2) void k_gemm_proj() {
    extern __shared__ __nv_bfloat16 sm[];
    __shared__ int s_ro[128];
    const int b = blockIdx.z;
    const int cnt = g_cnt[b];
    const int m0 = blockIdx.y * BM;
    if (m0 >= cnt) return;
    const int n0 = blockIdx.x * BN;
    const int tid = threadIdx.x;
    if (tid < 128) s_ro[tid] = (b * LL + g_idx[b][m0 + tid]) * H2;
    __syncthreads();

    float acc[4][4][4] = {};
    gemm_main(acc, sm, g_jh, g_jl, s_ro, g_wph, g_wpl, HH, HH, n0);

    const int lane = tid & 31, warp = tid >> 5;
    const int wm = warp & 1, wn = warp >> 1;
    const int r = lane >> 2, c = (lane & 3) * 2;
#pragma unroll
    for (int mt = 0; mt < 4; ++mt)
#pragma unroll
        for (int nt = 0; nt < 4; ++nt)
#pragma unroll
            for (int half = 0; half < 2; ++half) {
                int m = m0 + wm * 64 + mt * 16 + r + half * 8;
                int n = n0 + wn * 32 + nt * 8 + c;
                float2 bb = *(const float2*)&g_bpr[n];
                float v0 = fmaxf(acc[mt][nt][half * 2 + 0] + bb.x, 0.f);
                float v1 = fmaxf(acc[mt][nt][half * 2 + 1] + bb.y, 0.f);
                int f = n >> 9, h = n & 511;
                size_t o = (((size_t)(b * FF + f)) * LL + m) * HH + h;
                __nv_bfloat16 h0, l0, h1, l1;
                split2(v0, h0, l0); split2(v1, h1, l1);
                __nv_bfloat162 hv; hv.x = h0; hv.y = h1;
                __nv_bfloat162 lv; lv.x = l0; lv.y = l1;
                *(__nv_bfloat162*)&g_yh[o] = hv;
                *(__nv_bfloat162*)&g_yl[o] = lv;
            }
}

// scores (compact, per-factor, K-split): stream q = f*2 + khalf computes
// Yf[:, kh*256:(kh+1)*256] partial Gram. grid (36, 8, BB)
__global__ __launch_bounds__(256, 2) void k_gemm_scores() {
    extern __shared__ __nv_bfloat16 sm[];
    __shared__ int s_ro[128];
    const int b = blockIdx.z;
    const int q = blockIdx.y;          // 0..7
    const int f = q >> 1, kh = q & 1;
    const int koff = kh * 256;
    const int cnt = g_cnt[b];
    int t = blockIdx.x, bi = 0, rowlen = 8;
    while (t >= rowlen) { t -= rowlen; --rowlen; ++bi; }
    const int bj = bi + t;
    const int m0 = bi * BM, n0 = bj * BN;
    if (m0 >= cnt || n0 >= cnt) return;
    const int tid = threadIdx.x;
    if (tid < 128) s_ro[tid] = (m0 + tid) * HH + koff;
    __syncthreads();

    const __nv_bfloat16* Yh = g_yh + ((size_t)(b * FF + f)) * LL * HH;
    const __nv_bfloat16* Yl = g_yl + ((size_t)(b * FF + f)) * LL * HH;
    float acc[4][4][4] = {};
    gemm_main(acc, sm, Yh, Yl, s_ro, Yh + koff, Yl + koff, HH, 256, n0);

    float* Sb = g_Sf + (size_t)(q * BB + b) * LL * LL;
    const int lane = tid & 31, warp = tid >> 5;
    const int wm = warp & 1, wn = warp >> 1;
    const int r = lane >> 2, c = (lane & 3) * 2;
#pragma unroll
    for (int mt = 0; mt < 4; ++mt)
#pragma unroll
        for (int nt = 0; nt < 4; ++nt)
#pragma unroll
            for (int half = 0; half < 2; ++half) {
                int m = m0 + wm * 64 + mt * 16 + r + half * 8;
                int n = n0 + wn * 32 + nt * 8 + c;
                float v0 = acc[mt][nt][half * 2 + 0];
                float v1 = acc[mt][nt][half * 2 + 1];
                float2 fv; fv.x = v0; fv.y = v1;
                *(float2*)&Sb[(size_t)m * LL + n] = fv;
                if (bi != bj && m < cnt) {
                    if (n < cnt)     Sb[(size_t)n * LL + m] = v0;
                    if (n + 1 < cnt) Sb[(size_t)(n + 1) * LL + m] = v1;
                }
            }
}

// masked softmax; sums K-halves then maxes over f; Kp-bounded alpha writes
__global__ void k_softmax() {
    const int blk = blockIdx.x;
    const int b = blk >> 10, j = blk & 1023;
    const int cnt = g_cnt[b];
    if (j >= cnt) return;
    const int t = threadIdx.x;
    const float* S0 = g_Sf + (size_t)(b * LL + j) * LL;
    const size_t fs = (size_t)BB * LL * LL;
    int Kp = (cnt + 31) & ~31;
    if (Kp < 64) Kp = 64;

    float lm[4], msk[4];
    float mx = -CUDART_INF_F;
#pragma unroll
    for (int jj = 0; jj < 4; ++jj) {
        int m = t + jj * 256;
        float v = 0.f, mk = 0.f;
        if (m < cnt) {
            v = S0[m] + S0[fs + m];                              // f=0
            v = fmaxf(v, S0[2 * fs + m] + S0[3 * fs + m]);       // f=1
            v = fmaxf(v, S0[4 * fs + m] + S0[5 * fs + m]);       // f=2
            v = fmaxf(v, S0[6 * fs + m] + S0[7 * fs + m]);       // f=3
            mk = (m != j) ? 1.0f : 0.0f;
            v *= mk;
        }
        lm[jj] = v; msk[jj] = mk;
        mx = fmaxf(mx, v);
    }
    __shared__ float sh[256];
    __shared__ float2 sh2[256];
    sh[t] = mx; __syncthreads();
    for (int s = 128; s > 0; s >>= 1) {
        if (t < s) sh[t] = fmaxf(sh[t], sh[t + s]);
        __syncthreads();
    }
    const float rowmax = sh[0];
    __syncthreads();

    float e[4], z = 0.f, smv = 0.f;
#pragma unroll
    for (int jj = 0; jj < 4; ++jj) {
        e[jj] = expf(lm[jj] - rowmax);
        z += e[jj];
        smv += e[jj] * msk[jj];
    }
    float2 zz; zz.x = z; zz.y = smv;
    sh2[t] = zz; __syncthreads();
    for (int s = 128; s > 0; s >>= 1) {
        if (t < s) {
            float2 a = sh2[t], bq = sh2[t + s];
            a.x += bq.x; a.y += bq.y;
            sh2[t] = a;
        }
        __syncthreads();
    }
    const float Z  = sh2[0].x;
    const float SM = sh2[0].y;

    const float inv = 1024.0f / (SM + 1e-13f * Z);
#pragma unroll
    for (int jj = 0; jj < 4; ++jj) {
        int m = t + jj * 256;
        if (m >= Kp) continue;
        float a = e[jj] * msk[jj] * inv;
        __half hh, ll; split2h(a, hh, ll);
        size_t o = (size_t)(b * LL + j) * LL + m;
        g_ah16[o] = hh; g_al16[o] = ll;
    }
}

// enc (compact, 2-term fp16)
__global__ __launch_bounds__(256, 2) void k_gemm_enc() {
    extern __shared__ __half sm2[];
    __shared__ int s_ro[128];
    const int b = blockIdx.z;
    const int cnt = g_cnt[b];
    const int m0 = blockIdx.y * BM;
    if (m0 >= cnt) return;
    const int n0 = blockIdx.x * BN;
    const int tid = threadIdx.x;
    if (tid < 128) s_ro[tid] = (m0 + tid) * LL;
    __syncthreads();
    int Kp = (cnt + 31) & ~31;
    if (Kp < 64) Kp = 64;

    float acc[4][4][4] = {};
    gemm2_main(acc, sm2, g_ah16 + (size_t)b * LL * LL, g_al16 + (size_t)b * LL * LL, s_ro,
               g_xt16 + (size_t)b * HH * LL, LL, Kp, n0);

    const int lane = tid & 31, warp = tid >> 5;
    const int wm = warp & 1, wn = warp >> 1;
    const int r = lane >> 2, c = (lane & 3) * 2;
    const float sc = 1.0f / 1024.0f;
#pragma unroll
    for (int mt = 0; mt < 4; ++mt)
#pragma unroll
        for (int nt = 0; nt < 4; ++nt)
#pragma unroll
            for (int half = 0; half < 2; ++half) {
                int j = m0 + wm * 64 + mt * 16 + r + half * 8;
                if (j >= cnt) continue;
                int l = g_idx[b][j];
                int n = n0 + wn * 32 + nt * 8 + c;
                float v0 = acc[mt][nt][half * 2 + 0] * sc;
                float v1 = acc[mt][nt][half * 2 + 1] * sc;
                size_t o = ((size_t)b * LL + l) * H2 + HH + n;
                float2 fv; fv.x = v0; fv.y = v1;
                *(float2*)&g_joint[o] = fv;
                __half2 hv; hv.x = __float2half_rn(v0); hv.y = __float2half_rn(v1);
                *(__half2*)&g_j16[o] = hv;
            }
}

// gate (1-term fp16, row-partitioned): z<8 = active rows (K=1024), z>=8 = masked (K=512)
__global__ __launch_bounds__(256, 2) void k_gemm_gate(const float* __restrict__ X,
                                                      const float* __restrict__ bg,
                                                      float* __restrict__ out) {
    extern __shared__ __half sm1[];
    __shared__ int s_ro[128];
    __shared__ int s_l[128];
    const int z = blockIdx.z;
    const int b = z & 7;
    const bool act = z < 8;
    const int cnt = g_cnt[b];
    const int count = act ? cnt : (LL - cnt);
    const int m0 = blockIdx.y * BM;
    if (m0 >= count) return;
    const int Kdim = act ? H2 : HH;
    const int n0 = blockIdx.x * BN;
    const bool xhalf = (n0 < HH);
    const int tid = threadIdx.x;
    if (tid < 128) {
        int l = act ? g_idx[b][m0 + tid] : g_midx[b][m0 + tid];
        s_l[tid] = l;
        s_ro[tid] = (b * LL + l) * H2;
    }
    __syncthreads();

    float acc[4][4][4] = {};
    gemm1_main(acc, sm1, g_j16, s_ro, g_wg16, H2, Kdim, n0);

    const int lane = tid & 31, warp = tid >> 5;
    const int wm = warp & 1, wn = warp >> 1;
    const int r = lane >> 2, c = (lane & 3) * 2;
    const float sc = 1.0f / 32.0f;
#pragma unroll
    for (int mt = 0; mt < 4; ++mt)
#pragma unroll
        for (int nt = 0; nt < 4; ++nt)
#pragma unroll
            for (int half = 0; half < 2; ++half) {
                int jrow = wm * 64 + mt * 16 + r + half * 8;
                if (m0 + jrow >= count) continue;
                int l = s_l[jrow];
                int n = n0 + wn * 32 + nt * 8 + c;
                float2 bb = *(const float2*)&bg[n];
                float p0 = acc[mt][nt][half * 2 + 0] * sc + bb.x;
                float p1 = acc[mt][nt][half * 2 + 1] * sc + bb.y;
                float g0 = 1.0f / (1.0f + expf(-p0));
                float g1 = 1.0f / (1.0f + expf(-p1));
                size_t o = ((size_t)b * LL + l) * H2 + n;
                float2 jv;
                if (xhalf)       jv = *(const float2*)&X[((size_t)b * LL + l) * HH + n];
                else if (act)    jv = *(const float2*)&g_joint[o];
                else           { jv.x = 0.f; jv.y = 0.f; }
                float2 ov; ov.x = g0 * jv.x; ov.y = g1 * jv.y;
                *(float2*)&out[o] = ov;
            }
}

// ---------------- launch --------------------------------------------------------
extern "C" void kernel_launch(void* const* d_in, const int* in_sizes, int n_in,
                              void* d_out, int out_size) {
    const float* x  = (const float*)d_in[0];
    const int*   xm = (const int*)d_in[1];
    const float* Wp = (const float*)d_in[2];
    const float* bp = (const float*)d_in[3];
    const float* Wg = (const float*)d_in[4];
    const float* bg = (const float*)d_in[5];
    float* out = (float*)d_out;

    cudaFuncSetAttribute(k_gemm_proj,   cudaFuncAttributeMaxDynamicSharedMemorySize, SMEM_BYTES);
    cudaFuncSetAttribute(k_gemm_scores, cudaFuncAttributeMaxDynamicSharedMemorySize, SMEM_BYTES);
    cudaFuncSetAttribute(k_gemm_enc,    cudaFuncAttributeMaxDynamicSharedMemorySize, SMEM2_BYTES);
    cudaFuncSetAttribute(k_gemm_gate,   cudaFuncAttributeMaxDynamicSharedMemorySize, SMEM1_BYTES);

    k_compact<<<BB, 1024>>>(xm);

    dim3 tpre(32, 8);
    k_prep_x <<<dim3(HH / 32, LL / 32, BB), tpre>>>(x);
    k_prep_wp<<<dim3(HF / 32, HH / 32), tpre>>>(Wp, bp);
    k_prep_wg<<<dim3(H2 / 32, H2 / 32), tpre>>>(Wg);

    k_gemm_proj  <<<dim3(HF / BN, 8, BB), 256, SMEM_BYTES>>>();
    k_gemm_scores<<<dim3(36, 8, BB), 256, SMEM_BYTES>>>();
    k_softmax    <<<BB * LL, 256>>>();
    k_gemm_enc   <<<dim3(HH / BN, 8, BB), 256, SMEM2_BYTES>>>();
    k_gemm_gate  <<<dim3(H2 / BN, 8, 2 * BB), 256, SMEM1_BYTES>>>(x, bg, out);
}

// round 15
// speedup vs baseline: 1.0123x; 1.0123x over previous
#include <cuda_runtime.h>
#include <cuda_bf16.h>
#include <cuda_fp16.h>
#include <math_constants.h>
#include <cstdint>

// Shapes (fixed)
#define BB 8
#define LL 1024
#define HH 512
#define FF 4
#define HF 2048
#define H2 1024
#define MROWS 8192

// ---------------- scratch (device globals) ----------------------------------
__device__ __align__(256) float g_Sf[(size_t)FF * BB * LL * LL];   // per-factor compact scores
__device__ __align__(256) float g_joint[(size_t)MROWS * H2];       // enc half, active rows only
__device__ __align__(256) __nv_bfloat16 g_jh[(size_t)MROWS * H2];  // x bf16 hi/lo (proj A)
__device__ __align__(256) __nv_bfloat16 g_jl[(size_t)MROWS * H2];
__device__ __align__(256) __half g_j16[(size_t)MROWS * H2];        // joint fp16 single (gate A)
__device__ __align__(256) __half g_xt16[(size_t)BB * HH * LL];     // x^T compact cols (enc B)
__device__ __align__(256) __nv_bfloat16 g_wph[(size_t)HF * HH];
__device__ __align__(256) __nv_bfloat16 g_wpl[(size_t)HF * HH];
__device__ __align__(256) float g_bpr[HF];
__device__ __align__(256) __half g_wg16[(size_t)H2 * H2];          // Wgate^T fp16 x32
__device__ __align__(256) __nv_bfloat16 g_yh[(size_t)BB * FF * LL * HH];
__device__ __align__(256) __nv_bfloat16 g_yl[(size_t)BB * FF * LL * HH];
__device__ __align__(256) __half g_ah16[(size_t)BB * LL * LL];     // compact alpha x1024 hi/lo
__device__ __align__(256) __half g_al16[(size_t)BB * LL * LL];
// compaction
__device__ int g_idx[BB][LL];
__device__ int g_midx[BB][LL];
__device__ int g_cpos[BB * LL];
__device__ int g_cnt[BB];

// ---------------- helpers ----------------------------------------------------
__device__ __forceinline__ void split2(float v, __nv_bfloat16& h, __nv_bfloat16& l) {
    h = __float2bfloat16_rn(v);
    l = __float2bfloat16_rn(v - __bfloat162float(h));
}
__device__ __forceinline__ void split2h(float v, __half& h, __half& l) {
    h = __float2half_rn(v);
    l = __float2half_rn(v - __half2float(h));
}
__device__ __forceinline__ void cp16(void* smem, const void* gmem) {
    unsigned s = (unsigned)__cvta_generic_to_shared(smem);
    asm volatile("cp.async.cg.shared.global [%0], [%1], 16;\n" :: "r"(s), "l"(gmem));
}
__device__ __forceinline__ void cp_commit() { asm volatile("cp.async.commit_group;\n"); }
__device__ __forceinline__ void cp_wait0()  { asm volatile("cp.async.wait_group 0;\n"); }
__device__ __forceinline__ void cp_wait1()  { asm volatile("cp.async.wait_group 1;\n"); }

__device__ __forceinline__ void ldsm4(unsigned& r0, unsigned& r1, unsigned& r2, unsigned& r3,
                                      const void* p) {
    unsigned s = (unsigned)__cvta_generic_to_shared(p);
    asm volatile("ldmatrix.sync.aligned.m8n8.x4.shared.b16 {%0,%1,%2,%3}, [%4];\n"
                 : "=r"(r0), "=r"(r1), "=r"(r2), "=r"(r3) : "r"(s));
}
__device__ __forceinline__ void mma16816(float* c, const unsigned* a, const unsigned* b) {
    asm volatile(
        "mma.sync.aligned.m16n8k16.row.col.f32.bf16.bf16.f32 "
        "{%0,%1,%2,%3}, {%4,%5,%6,%7}, {%8,%9}, {%0,%1,%2,%3};\n"
        : "+f"(c[0]), "+f"(c[1]), "+f"(c[2]), "+f"(c[3])
        : "r"(a[0]), "r"(a[1]), "r"(a[2]), "r"(a[3]), "r"(b[0]), "r"(b[1]));
}
__device__ __forceinline__ void mma16816h(float* c, const unsigned* a, const unsigned* b) {
    asm volatile(
        "mma.sync.aligned.m16n8k16.row.col.f32.f16.f16.f32 "
        "{%0,%1,%2,%3}, {%4,%5,%6,%7}, {%8,%9}, {%0,%1,%2,%3};\n"
        : "+f"(c[0]), "+f"(c[1]), "+f"(c[2]), "+f"(c[3])
        : "r"(a[0]), "r"(a[1]), "r"(a[2]), "r"(a[3]), "r"(b[0]), "r"(b[1]));
}

// ---------------- shared tile geometry ----------------------------------------
#define BM 128
#define BN 128
#define BK 32
#define SSTR 40
#define TILE_E (128 * SSTR)

// ============ 3-term bf16 template (proj, scores): 4 tiles, 2 stages ==========
#define STAGE_E (4 * TILE_E)
#define SMEM_BYTES (2 * STAGE_E * 2)

__device__ __forceinline__ void load_stage(__nv_bfloat16* st,
                                           const __nv_bfloat16* Ah, const __nv_bfloat16* Al,
                                           const int* __restrict__ rowoff,
                                           const __nv_bfloat16* Bh, const __nv_bfloat16* Bl, int ldb,
                                           int n0, int kk, int tid) {
    __nv_bfloat16* sAH = st;
    __nv_bfloat16* sAL = st + TILE_E;
    __nv_bfloat16* sBH = st + 2 * TILE_E;
    __nv_bfloat16* sBL = st + 3 * TILE_E;
#pragma unroll
    for (int i = 0; i < 2; ++i) {
        int q = tid + i * 256;
        int r = q >> 2, c = (q & 3) * 8;
        size_t ga = (size_t)rowoff[r] + kk + c;
        size_t gb = (size_t)(n0 + r) * ldb + kk + c;
        cp16(&sAH[r * SSTR + c], &Ah[ga]);
        cp16(&sAL[r * SSTR + c], &Al[ga]);
        cp16(&sBH[r * SSTR + c], &Bh[gb]);
        cp16(&sBL[r * SSTR + c], &Bl[gb]);
    }
    cp_commit();
}

__device__ __forceinline__ void compute_stage(float (&acc)[4][4][4],
                                              const __nv_bfloat16* st,
                                              int wm, int wn, int lane) {
    const __nv_bfloat16* sAH = st;
    const __nv_bfloat16* sAL = st + TILE_E;
    const __nv_bfloat16* sBH = st + 2 * TILE_E;
    const __nv_bfloat16* sBL = st + 3 * TILE_E;
#pragma unroll
    for (int ks = 0; ks < 2; ++ks) {
        const int col = ks * 16 + (lane >> 4) * 8;
        const int arow = wm * 64 + (lane & 15);
        const int brow = wn * 32 + (lane & 15);
        unsigned ah[4][4], al[4][4], bh[4][2], bl[4][2];
#pragma unroll
        for (int mt = 0; mt < 4; ++mt) {
            ldsm4(ah[mt][0], ah[mt][1], ah[mt][2], ah[mt][3], &sAH[(arow + mt * 16) * SSTR + col]);
            ldsm4(al[mt][0], al[mt][1], al[mt][2], al[mt][3], &sAL[(arow + mt * 16) * SSTR + col]);
        }
#pragma unroll
        for (int np = 0; np < 2; ++np) {
            unsigned r0, r1, r2, r3;
            ldsm4(r0, r1, r2, r3, &sBH[(brow + np * 16) * SSTR + col]);
            bh[np * 2 + 0][0] = r0; bh[np * 2 + 1][0] = r1;
            bh[np * 2 + 0][1] = r2; bh[np * 2 + 1][1] = r3;
            ldsm4(r0, r1, r2, r3, &sBL[(brow + np * 16) * SSTR + col]);
            bl[np * 2 + 0][0] = r0; bl[np * 2 + 1][0] = r1;
            bl[np * 2 + 0][1] = r2; bl[np * 2 + 1][1] = r3;
        }
#pragma unroll
        for (int mt = 0; mt < 4; ++mt)
#pragma unroll
            for (int nt = 0; nt < 4; ++nt)
                mma16816(acc[mt][nt], ah[mt], bh[nt]);
#pragma unroll
        for (int mt = 0; mt < 4; ++mt)
#pragma unroll
            for (int nt = 0; nt < 4; ++nt)
                mma16816(acc[mt][nt], ah[mt], bl[nt]);
#pragma unroll
        for (int mt = 0; mt < 4; ++mt)
#pragma unroll
            for (int nt = 0; nt < 4; ++nt)
                mma16816(acc[mt][nt], al[mt], bh[nt]);
    }
}

__device__ __forceinline__ void gemm_main(float (&acc)[4][4][4], __nv_bfloat16* sm,
                                          const __nv_bfloat16* Ah, const __nv_bfloat16* Al,
                                          const int* __restrict__ rowoff,
                                          const __nv_bfloat16* Bh, const __nv_bfloat16* Bl, int ldb,
                                          int K, int n0) {
    const int tid = threadIdx.x;
    const int lane = tid & 31, warp = tid >> 5;
    const int wm = warp & 1, wn = warp >> 1;
    const int S = K / BK;

    load_stage(sm, Ah, Al, rowoff, Bh, Bl, ldb, n0, 0, tid);
    for (int s = 0; s < S; ++s) {
        cp_wait0();
        __syncthreads();
        if (s + 1 < S)
            load_stage(sm + ((s + 1) & 1) * STAGE_E, Ah, Al, rowoff, Bh, Bl, ldb,
                       n0, (s + 1) * BK, tid);
        compute_stage(acc, sm + (s & 1) * STAGE_E, wm, wn, lane);
    }
}

// ============ 2-term fp16 template (enc): 3 tiles, 3 stages ====================
#define STAGE2_E (3 * TILE_E)
#define SMEM2_BYTES (3 * STAGE2_E * 2)

__device__ __forceinline__ void load_stage2(__half* st,
                                            const __half* Ah, const __half* Al,
                                            const int* __restrict__ rowoff,
                                            const __half* B, int ldb,
                                            int n0, int kk, int tid) {
    __half* sAH = st;
    __half* sAL = st + TILE_E;
    __half* sB  = st + 2 * TILE_E;
#pragma unroll
    for (int i = 0; i < 2; ++i) {
        int q = tid + i * 256;
        int r = q >> 2, c = (q & 3) * 8;
        size_t ga = (size_t)rowoff[r] + kk + c;
        size_t gb = (size_t)(n0 + r) * ldb + kk + c;
        cp16(&sAH[r * SSTR + c], &Ah[ga]);
        cp16(&sAL[r * SSTR + c], &Al[ga]);
        cp16(&sB[r * SSTR + c], &B[gb]);
    }
    cp_commit();
}

__device__ __forceinline__ void compute_stage2(float (&acc)[4][4][4],
                                               const __half* st,
                                               int wm, int wn, int lane) {
    const __half* sAH = st;
    const __half* sAL = st + TILE_E;
    const __half* sB  = st + 2 * TILE_E;
#pragma unroll
    for (int ks = 0; ks < 2; ++ks) {
        const int col = ks * 16 + (lane >> 4) * 8;
        const int arow = wm * 64 + (lane & 15);
        const int brow = wn * 32 + (lane & 15);
        unsigned ah[4][4], al[4][4], bb[4][2];
#pragma unroll
        for (int mt = 0; mt < 4; ++mt) {
            ldsm4(ah[mt][0], ah[mt][1], ah[mt][2], ah[mt][3], &sAH[(arow + mt * 16) * SSTR + col]);
            ldsm4(al[mt][0], al[mt][1], al[mt][2], al[mt][3], &sAL[(arow + mt * 16) * SSTR + col]);
        }
#pragma unroll
        for (int np = 0; np < 2; ++np) {
            unsigned r0, r1, r2, r3;
            ldsm4(r0, r1, r2, r3, &sB[(brow + np * 16) * SSTR + col]);
            bb[np * 2 + 0][0] = r0; bb[np * 2 + 1][0] = r1;
            bb[np * 2 + 0][1] = r2; bb[np * 2 + 1][1] = r3;
        }
#pragma unroll
        for (int mt = 0; mt < 4; ++mt)
#pragma unroll
            for (int nt = 0; nt < 4; ++nt)
                mma16816h(acc[mt][nt], ah[mt], bb[nt]);
#pragma unroll
        for (int mt = 0; mt < 4; ++mt)
#pragma unroll
            for (int nt = 0; nt < 4; ++nt)
                mma16816h(acc[mt][nt], al[mt], bb[nt]);
    }
}

__device__ __forceinline__ void gemm2_main(float (&acc)[4][4][4], __half* sm,
                                           const __half* Ah, const __half* Al,
                                           const int* __restrict__ rowoff,
                                           const __half* B, int ldb,
                                           int K, int n0) {
    const int tid = threadIdx.x;
    const int lane = tid & 31, warp = tid >> 5;
    const int wm = warp & 1, wn = warp >> 1;
    const int S = K / BK;

    load_stage2(sm, Ah, Al, rowoff, B, ldb, n0, 0, tid);
    load_stage2(sm + STAGE2_E, Ah, Al, rowoff, B, ldb, n0, BK, tid);
    for (int s = 0; s < S; ++s) {
        if (s + 2 < S) cp_wait1(); else cp_wait0();
        __syncthreads();
        if (s + 2 < S)
            load_stage2(sm + (uint32_t)((s + 2) % 3) * STAGE2_E, Ah, Al, rowoff, B, ldb,
                        n0, (s + 2) * BK, tid);
        compute_stage2(acc, sm + (uint32_t)(s % 3) * STAGE2_E, wm, wn, lane);
    }
}

// ============ 1-term fp16 template (gate): 2 tiles, 3 stages ===================
#define STAGE1_E (2 * TILE_E)
#define SMEM1_BYTES (3 * STAGE1_E * 2)

__device__ __forceinline__ void load_stage1(__half* st,
                                            const __half* A,
                                            const int* __restrict__ rowoff,
                                            const __half* B, int ldb,
                                            int n0, int kk, int tid) {
    __half* sA = st;
    __half* sB = st + TILE_E;
#pragma unroll
    for (int i = 0; i < 2; ++i) {
        int q = tid + i * 256;
        int r = q >> 2, c = (q & 3) * 8;
        size_t ga = (size_t)rowoff[r] + kk + c;
        size_t gb = (size_t)(n0 + r) * ldb + kk + c;
        cp16(&sA[r * SSTR + c], &A[ga]);
        cp16(&sB[r * SSTR + c], &B[gb]);
    }
    cp_commit();
}

__device__ __forceinline__ void compute_stage1(float (&acc)[4][4][4],
                                               const __half* st,
                                               int wm, int wn, int lane) {
    const __half* sA = st;
    const __half* sB = st + TILE_E;
#pragma unroll
    for (int ks = 0; ks < 2; ++ks) {
        const int col = ks * 16 + (lane >> 4) * 8;
        const int arow = wm * 64 + (lane & 15);
        const int brow = wn * 32 + (lane & 15);
        unsigned aa[4][4], bb[4][2];
#pragma unroll
        for (int mt = 0; mt < 4; ++mt)
            ldsm4(aa[mt][0], aa[mt][1], aa[mt][2], aa[mt][3], &sA[(arow + mt * 16) * SSTR + col]);
#pragma unroll
        for (int np = 0; np < 2; ++np) {
            unsigned r0, r1, r2, r3;
            ldsm4(r0, r1, r2, r3, &sB[(brow + np * 16) * SSTR + col]);
            bb[np * 2 + 0][0] = r0; bb[np * 2 + 1][0] = r1;
            bb[np * 2 + 0][1] = r2; bb[np * 2 + 1][1] = r3;
        }
#pragma unroll
        for (int mt = 0; mt < 4; ++mt)
#pragma unroll
            for (int nt = 0; nt < 4; ++nt)
                mma16816h(acc[mt][nt], aa[mt], bb[nt]);
    }
}

__device__ __forceinline__ void gemm1_main(float (&acc)[4][4][4], __half* sm,
                                           const __half* A,
                                           const int* __restrict__ rowoff,
                                           const __half* B, int ldb,
                                           int K, int n0) {
    const int tid = threadIdx.x;
    const int lane = tid & 31, warp = tid >> 5;
    const int wm = warp & 1, wn = warp >> 1;
    const int S = K / BK;

    load_stage1(sm, A, rowoff, B, ldb, n0, 0, tid);
    load_stage1(sm + STAGE1_E, A, rowoff, B, ldb, n0, BK, tid);
    for (int s = 0; s < S; ++s) {
        if (s + 2 < S) cp_wait1(); else cp_wait0();
        __syncthreads();
        if (s + 2 < S)
            load_stage1(sm + (uint32_t)((s + 2) % 3) * STAGE1_E, A, rowoff, B, ldb,
                        n0, (s + 2) * BK, tid);
        compute_stage1(acc, sm + (uint32_t)(s % 3) * STAGE1_E, wm, wn, lane);
    }
}

// ---------------- compaction -----------------------------------------------
__global__ void k_compact(const int* __restrict__ xmask) {
    const int b = blockIdx.x;
    const int t = threadIdx.x;
    __shared__ int sc[1024];
    int m = xmask[b * LL + t];
    sc[t] = m;
    __syncthreads();
    for (int off = 1; off < 1024; off <<= 1) {
        int v = (t >= off) ? sc[t - off] : 0;
        __syncthreads();
        sc[t] += v;
        __syncthreads();
    }
    int pos = sc[t] - m;
    if (m) { g_idx[b][pos] = t; g_cpos[b * LL + t] = pos; }
    else   { g_midx[b][t - sc[t]] = t; g_cpos[b * LL + t] = -1; }
    int c = sc[1023];
    if (t == 0) g_cnt[b] = c;
    if (t >= c)      g_idx[b][t] = 0;
    if (t >= LL - c) g_midx[b][t] = 0;
}

// ---------------- prep kernels -----------------------------------------------
__global__ void k_prep_x(const float* __restrict__ X) {
    __shared__ float tile[32][33];
    const int b = blockIdx.z;
    const int l0 = blockIdx.y * 32, h0 = blockIdx.x * 32;
    const int tx = threadIdx.x, ty = threadIdx.y;
#pragma unroll
    for (int i = 0; i < 4; ++i) {
        int l = l0 + ty + 8 * i;
        float v = X[((size_t)b * LL + l) * HH + h0 + tx];
        tile[ty + 8 * i][tx] = v;
        size_t jo = ((size_t)b * LL + l) * H2 + h0 + tx;
        __nv_bfloat16 hh, ll; split2(v, hh, ll);
        g_jh[jo] = hh; g_jl[jo] = ll;
        g_j16[jo] = __float2half_rn(v);
    }
    __syncthreads();
#pragma unroll
    for (int i = 0; i < 4; ++i) {
        int h = h0 + ty + 8 * i;
        int l = l0 + tx;
        float v = tile[tx][ty + 8 * i];
        int p = g_cpos[b * LL + l];
        if (p >= 0)
            g_xt16[((size_t)b * HH + h) * LL + p] = __float2half_rn(v);
    }
}

// merged weight prep: z = 0..15 -> Wproj tile rows; z = 16..17 -> Wgate halves
__global__ void k_prep_w(const float* __restrict__ Wp, const float* __restrict__ bp,
                         const float* __restrict__ Wg) {
    __shared__ float tile[32][33];
    const int tx = threadIdx.x, ty = threadIdx.y;
    if (blockIdx.z < 16) {
        const int k0 = blockIdx.z * 32, n0 = blockIdx.x * 32;   // gridDim.x = 64
#pragma unroll
        for (int i = 0; i < 4; ++i)
            tile[ty + 8 * i][tx] = Wp[(size_t)(k0 + ty + 8 * i) * HF + n0 + tx];
        __syncthreads();
#pragma unroll
        for (int i = 0; i < 4; ++i) {
            int n = n0 + ty + 8 * i;
            int np = ((n & 3) << 9) + (n >> 2);
            float v = tile[tx][ty + 8 * i];
            __nv_bfloat16 hh, ll; split2(v, hh, ll);
            size_t o = (size_t)np * HH + k0 + tx;
            g_wph[o] = hh; g_wpl[o] = ll;
            if (k0 == 0 && tx == 0) g_bpr[np] = bp[n];
        }
    } else {
        const int zz = blockIdx.z - 16;                          // 0..1
        const int k0 = (zz * 32 + blockIdx.x / 2) * 32 % H2;     // decode below instead
        // simpler decode: linear block id over 32x32 grid of Wgate
        const int blk = zz * 64 + blockIdx.x;                    // 0..127 ... need 1024 blocks
        // Wgate needs 32x32 = 1024 tiles; we fold them over gridDim.x=64, z in {16..31}
        (void)k0; (void)blk;
    }
}

// Wgate prep kept separate for correctness (decode above too cramped); still one
// fewer launch overall is abandoned — keep original simple kernel.
__global__ void k_prep_wg(const float* __restrict__ W) {
    __shared__ float tile[32][33];
    const int k0 = blockIdx.y * 32, n0 = blockIdx.x * 32;
    const int tx = threadIdx.x, ty = threadIdx.y;
#pragma unroll
    for (int i = 0; i < 4; ++i)
        tile[ty + 8 * i][tx] = W[(size_t)(k0 + ty + 8 * i) * H2 + n0 + tx];
    __syncthreads();
#pragma unroll
    for (int i = 0; i < 4; ++i) {
        int n = n0 + ty + 8 * i;
        float v = tile[tx][ty + 8 * i];
        g_wg16[(size_t)n * H2 + k0 + tx] = __float2half_rn(32.0f * v);
    }
}

// ---------------- GEMM kernels -------------------------------------------------
// proj (compact rows)
__global__ __launch_bounds__(256, 2) void k_gemm_proj() {
    extern __shared__ __nv_bfloat16 sm[];
    __shared__ int s_ro[128];
    const int b = blockIdx.z;
    const int cnt = g_cnt[b];
    const int m0 = blockIdx.y * BM;
    if (m0 >= cnt) return;
    const int n0 = blockIdx.x * BN;
    const int tid = threadIdx.x;
    if (tid < 128) s_ro[tid] = (b * LL + g_idx[b][m0 + tid]) * H2;
    __syncthreads();

    float acc[4][4][4] = {};
    gemm_main(acc, sm, g_jh, g_jl, s_ro, g_wph, g_wpl, HH, HH, n0);

    const int lane = tid & 31, warp = tid >> 5;
    const int wm = warp & 1, wn = warp >> 1;
    const int r = lane >> 2, c = (lane & 3) * 2;
#pragma unroll
    for (int mt = 0; mt < 4; ++mt)
#pragma unroll
        for (int nt = 0; nt < 4; ++nt)
#pragma unroll
            for (int half = 0; half < 2; ++half) {
                int m = m0 + wm * 64 + mt * 16 + r + half * 8;
                int n = n0 + wn * 32 + nt * 8 + c;
                float2 bb = *(const float2*)&g_bpr[n];
                float v0 = fmaxf(acc[mt][nt][half * 2 + 0] + bb.x, 0.f);
                float v1 = fmaxf(acc[mt][nt][half * 2 + 1] + bb.y, 0.f);
                int f = n >> 9, h = n & 511;
                size_t o = (((size_t)(b * FF + f)) * LL + m) * HH + h;
                __nv_bfloat16 h0, l0, h1, l1;
                split2(v0, h0, l0); split2(v1, h1, l1);
                __nv_bfloat162 hv; hv.x = h0; hv.y = h1;
                __nv_bfloat162 lv; lv.x = l0; lv.y = l1;
                *(__nv_bfloat162*)&g_yh[o] = hv;
                *(__nv_bfloat162*)&g_yl[o] = lv;
            }
}

// scores (compact, per-factor): Sf = Yf Yf^T upper tiles + mirror. grid (36, FF, BB)
__global__ __launch_bounds__(256, 2) void k_gemm_scores() {
    extern __shared__ __nv_bfloat16 sm[];
    __shared__ int s_ro[128];
    const int b = blockIdx.z;
    const int f = blockIdx.y;
    const int cnt = g_cnt[b];
    int t = blockIdx.x, bi = 0, rowlen = 8;
    while (t >= rowlen) { t -= rowlen; --rowlen; ++bi; }
    const int bj = bi + t;
    const int m0 = bi * BM, n0 = bj * BN;
    if (m0 >= cnt || n0 >= cnt) return;
    const int tid = threadIdx.x;
    if (tid < 128) s_ro[tid] = (m0 + tid) * HH;
    __syncthreads();

    const __nv_bfloat16* Yh = g_yh + ((size_t)(b * FF + f)) * LL * HH;
    const __nv_bfloat16* Yl = g_yl + ((size_t)(b * FF + f)) * LL * HH;
    float acc[4][4][4] = {};
    gemm_main(acc, sm, Yh, Yl, s_ro, Yh, Yl, HH, HH, n0);

    float* Sb = g_Sf + (size_t)(f * BB + b) * LL * LL;
    const int lane = tid & 31, warp = tid >> 5;
    const int wm = warp & 1, wn = warp >> 1;
    const int r = lane >> 2, c = (lane & 3) * 2;
#pragma unroll
    for (int mt = 0; mt < 4; ++mt)
#pragma unroll
        for (int nt = 0; nt < 4; ++nt)
#pragma unroll
            for (int half = 0; half < 2; ++half) {
                int m = m0 + wm * 64 + mt * 16 + r + half * 8;
                int n = n0 + wn * 32 + nt * 8 + c;
                float v0 = acc[mt][nt][half * 2 + 0];
                float v1 = acc[mt][nt][half * 2 + 1];
                float2 fv; fv.x = v0; fv.y = v1;
                *(float2*)&Sb[(size_t)m * LL + n] = fv;
                if (bi != bj && m < cnt) {
                    if (n < cnt)     Sb[(size_t)n * LL + m] = v0;
                    if (n + 1 < cnt) Sb[(size_t)(n + 1) * LL + m] = v1;
                }
            }
}

// masked softmax; shuffle-based tail reductions; Kp-bounded alpha writes
__global__ void k_softmax() {
    const int blk = blockIdx.x;
    const int b = blk >> 10, j = blk & 1023;
    const int cnt = g_cnt[b];
    if (j >= cnt) return;
    const int t = threadIdx.x;
    const int lane = t & 31, warp = t >> 5;
    const float* S0 = g_Sf + (size_t)(b * LL + j) * LL;
    const size_t fs = (size_t)BB * LL * LL;
    int Kp = (cnt + 31) & ~31;
    if (Kp < 64) Kp = 64;

    float lm[4], msk[4];
    float mx = -CUDART_INF_F;
#pragma unroll
    for (int jj = 0; jj < 4; ++jj) {
        int m = t + jj * 256;
        float v = 0.f, mk = 0.f;
        if (m < cnt) {
            v = S0[m];
            v = fmaxf(v, S0[fs + m]);
            v = fmaxf(v, S0[2 * fs + m]);
            v = fmaxf(v, S0[3 * fs + m]);
            mk = (m != j) ? 1.0f : 0.0f;
            v *= mk;
        }
        lm[jj] = v; msk[jj] = mk;
        mx = fmaxf(mx, v);
    }
    __shared__ float shm[8];
    __shared__ float2 shz[8];
#pragma unroll
    for (int s = 16; s > 0; s >>= 1)
        mx = fmaxf(mx, __shfl_xor_sync(0xffffffffu, mx, s));
    if (lane == 0) shm[warp] = mx;
    __syncthreads();
    float rowmax = shm[lane & 7];
#pragma unroll
    for (int s = 4; s > 0; s >>= 1)
        rowmax = fmaxf(rowmax, __shfl_xor_sync(0xffffffffu, rowmax, s));

    float e[4], z = 0.f, smv = 0.f;
#pragma unroll
    for (int jj = 0; jj < 4; ++jj) {
        e[jj] = __expf(lm[jj] - rowmax);
        z += e[jj];
        smv += e[jj] * msk[jj];
    }
#pragma unroll
    for (int s = 16; s > 0; s >>= 1) {
        z   += __shfl_xor_sync(0xffffffffu, z, s);
        smv += __shfl_xor_sync(0xffffffffu, smv, s);
    }
    if (lane == 0) { float2 p; p.x = z; p.y = smv; shz[warp] = p; }
    __syncthreads();
    float2 acc2 = shz[lane & 7];
#pragma unroll
    for (int s = 4; s > 0; s >>= 1) {
        acc2.x += __shfl_xor_sync(0xffffffffu, acc2.x, s);
        acc2.y += __shfl_xor_sync(0xffffffffu, acc2.y, s);
    }
    const float Z = acc2.x, SM = acc2.y;

    const float inv = 1024.0f / (SM + 1e-13f * Z);
#pragma unroll
    for (int jj = 0; jj < 4; ++jj) {
        int m = t + jj * 256;
        if (m >= Kp) continue;
        float a = e[jj] * msk[jj] * inv;
        __half hh, ll; split2h(a, hh, ll);
        size_t o = (size_t)(b * LL + j) * LL + m;
        g_ah16[o] = hh; g_al16[o] = ll;
    }
}

// enc (compact, 2-term fp16)
__global__ __launch_bounds__(256, 2) void k_gemm_enc() {
    extern __shared__ __half sm2[];
    __shared__ int s_ro[128];
    const int b = blockIdx.z;
    const int cnt = g_cnt[b];
    const int m0 = blockIdx.y * BM;
    if (m0 >= cnt) return;
    const int n0 = blockIdx.x * BN;
    const int tid = threadIdx.x;
    if (tid < 128) s_ro[tid] = (m0 + tid) * LL;
    __syncthreads();
    int Kp = (cnt + 31) & ~31;
    if (Kp < 64) Kp = 64;

    float acc[4][4][4] = {};
    gemm2_main(acc, sm2, g_ah16 + (size_t)b * LL * LL, g_al16 + (size_t)b * LL * LL, s_ro,
               g_xt16 + (size_t)b * HH * LL, LL, Kp, n0);

    const int lane = tid & 31, warp = tid >> 5;
    const int wm = warp & 1, wn = warp >> 1;
    const int r = lane >> 2, c = (lane & 3) * 2;
    const float sc = 1.0f / 1024.0f;
#pragma unroll
    for (int mt = 0; mt < 4; ++mt)
#pragma unroll
        for (int nt = 0; nt < 4; ++nt)
#pragma unroll
            for (int half = 0; half < 2; ++half) {
                int j = m0 + wm * 64 + mt * 16 + r + half * 8;
                if (j >= cnt) continue;
                int l = g_idx[b][j];
                int n = n0 + wn * 32 + nt * 8 + c;
                float v0 = acc[mt][nt][half * 2 + 0] * sc;
                float v1 = acc[mt][nt][half * 2 + 1] * sc;
                size_t o = ((size_t)b * LL + l) * H2 + HH + n;
                float2 fv; fv.x = v0; fv.y = v1;
                *(float2*)&g_joint[o] = fv;
                __half2 hv; hv.x = __float2half_rn(v0); hv.y = __float2half_rn(v1);
                *(__half2*)&g_j16[o] = hv;
            }
}

// gate (1-term fp16, row-partitioned): z<8 = active rows (K=1024), z>=8 = masked (K=512)
__global__ __launch_bounds__(256, 2) void k_gemm_gate(const float* __restrict__ X,
                                                      const float* __restrict__ bg,
                                                      float* __restrict__ out) {
    extern __shared__ __half sm1[];
    __shared__ int s_ro[128];
    __shared__ int s_l[128];
    const int z = blockIdx.z;
    const int b = z & 7;
    const bool act = z < 8;
    const int cnt = g_cnt[b];
    const int count = act ? cnt : (LL - cnt);
    const int m0 = blockIdx.y * BM;
    if (m0 >= count) return;
    const int Kdim = act ? H2 : HH;
    const int n0 = blockIdx.x * BN;
    const bool xhalf = (n0 < HH);
    const int tid = threadIdx.x;
    if (tid < 128) {
        int l = act ? g_idx[b][m0 + tid] : g_midx[b][m0 + tid];
        s_l[tid] = l;
        s_ro[tid] = (b * LL + l) * H2;
    }
    __syncthreads();

    float acc[4][4][4] = {};
    gemm1_main(acc, sm1, g_j16, s_ro, g_wg16, H2, Kdim, n0);

    const int lane = tid & 31, warp = tid >> 5;
    const int wm = warp & 1, wn = warp >> 1;
    const int r = lane >> 2, c = (lane & 3) * 2;
    const float sc = 1.0f / 32.0f;
#pragma unroll
    for (int mt = 0; mt < 4; ++mt)
#pragma unroll
        for (int nt = 0; nt < 4; ++nt)
#pragma unroll
            for (int half = 0; half < 2; ++half) {
                int jrow = wm * 64 + mt * 16 + r + half * 8;
                if (m0 + jrow >= count) continue;
                int l = s_l[jrow];
                int n = n0 + wn * 32 + nt * 8 + c;
                float2 bb = *(const float2*)&bg[n];
                float p0 = acc[mt][nt][half * 2 + 0] * sc + bb.x;
                float p1 = acc[mt][nt][half * 2 + 1] * sc + bb.y;
                float g0 = 1.0f / (1.0f + __expf(-p0));
                float g1 = 1.0f / (1.0f + __expf(-p1));
                size_t o = ((size_t)b * LL + l) * H2 + n;
                float2 jv;
                if (xhalf)       jv = *(const float2*)&X[((size_t)b * LL + l) * HH + n];
                else if (act)    jv = *(const float2*)&g_joint[o];
                else           { jv.x = 0.f; jv.y = 0.f; }
                float2 ov; ov.x = g0 * jv.x; ov.y = g1 * jv.y;
                *(float2*)&out[o] = ov;
            }
}

// Wproj prep (restored simple version; merged variant above unused)
__global__ void k_prep_wp(const float* __restrict__ W, const float* __restrict__ bp) {
    __shared__ float tile[32][33];
    const int k0 = blockIdx.y * 32, n0 = blockIdx.x * 32;
    const int tx = threadIdx.x, ty = threadIdx.y;
#pragma unroll
    for (int i = 0; i < 4; ++i)
        tile[ty + 8 * i][tx] = W[(size_t)(k0 + ty + 8 * i) * HF + n0 + tx];
    __syncthreads();
#pragma unroll
    for (int i = 0; i < 4; ++i) {
        int n = n0 + ty + 8 * i;
        int np = ((n & 3) << 9) + (n >> 2);
        float v = tile[tx][ty + 8 * i];
        __nv_bfloat16 hh, ll; split2(v, hh, ll);
        size_t o = (size_t)np * HH + k0 + tx;
        g_wph[o] = hh; g_wpl[o] = ll;
        if (k0 == 0 && tx == 0) g_bpr[np] = bp[n];
    }
}

// ---------------- launch --------------------------------------------------------
extern "C" void kernel_launch(void* const* d_in, const int* in_sizes, int n_in,
                              void* d_out, int out_size) {
    const float* x  = (const float*)d_in[0];
    const int*   xm = (const int*)d_in[1];
    const float* Wp = (const float*)d_in[2];
    const float* bp = (const float*)d_in[3];
    const float* Wg = (const float*)d_in[4];
    const float* bg = (const float*)d_in[5];
    float* out = (float*)d_out;

    cudaFuncSetAttribute(k_gemm_proj,   cudaFuncAttributeMaxDynamicSharedMemorySize, SMEM_BYTES);
    cudaFuncSetAttribute(k_gemm_scores, cudaFuncAttributeMaxDynamicSharedMemorySize, SMEM_BYTES);
    cudaFuncSetAttribute(k_gemm_enc,    cudaFuncAttributeMaxDynamicSharedMemorySize, SMEM2_BYTES);
    cudaFuncSetAttribute(k_gemm_gate,   cudaFuncAttributeMaxDynamicSharedMemorySize, SMEM1_BYTES);

    k_compact<<<BB, 1024>>>(xm);

    dim3 tpre(32, 8);
    k_prep_x <<<dim3(HH / 32, LL / 32, BB), tpre>>>(x);
    k_prep_wp<<<dim3(HF / 32, HH / 32), tpre>>>(Wp, bp);
    k_prep_wg<<<dim3(H2 / 32, H2 / 32), tpre>>>(Wg);

    k_gemm_proj  <<<dim3(HF / BN, 8, BB), 256, SMEM_BYTES>>>();
    k_gemm_scores<<<dim3(36, FF, BB), 256, SMEM_BYTES>>>();
    k_softmax    <<<BB * LL, 256>>>();
    k_gemm_enc   <<<dim3(HH / BN, 8, BB), 256, SMEM2_BYTES>>>();
    k_gemm_gate  <<<dim3(H2 / BN, 8, 2 * BB), 256, SMEM1_BYTES>>>(x, bg, out);
}

// round 16
// speedup vs baseline: 1.0222x; 1.0098x over previous
#include <cuda_runtime.h>
#include <cuda_bf16.h>
#include <cuda_fp16.h>
#include <math_constants.h>
#include <cstdint>

// Shapes (fixed)
#define BB 8
#define LL 1024
#define HH 512
#define FF 4
#define HF 2048
#define H2 1024
#define MROWS 8192

// ---------------- scratch (device globals) ----------------------------------
__device__ __align__(256) float g_Sf[(size_t)FF * BB * LL * LL];   // per-factor compact scores
__device__ __align__(256) float g_joint[(size_t)MROWS * H2];       // enc half, active rows only
__device__ __align__(256) __nv_bfloat16 g_jh[(size_t)MROWS * H2];  // x bf16 hi/lo (proj A)
__device__ __align__(256) __nv_bfloat16 g_jl[(size_t)MROWS * H2];
__device__ __align__(256) __half g_j16[(size_t)MROWS * H2];        // joint fp16 single (gate A)
__device__ __align__(256) __half g_xt16[(size_t)BB * HH * LL];     // x^T compact cols (enc B)
__device__ __align__(256) __nv_bfloat16 g_wph[(size_t)HF * HH];
__device__ __align__(256) __nv_bfloat16 g_wpl[(size_t)HF * HH];
__device__ __align__(256) float g_bpr[HF];
__device__ __align__(256) __half g_wg16[(size_t)H2 * H2];          // Wgate^T fp16 x32
__device__ __align__(256) __nv_bfloat16 g_yh[(size_t)BB * FF * LL * HH];
__device__ __align__(256) __nv_bfloat16 g_yl[(size_t)BB * FF * LL * HH];
__device__ __align__(256) __half g_ah16[(size_t)BB * LL * LL];     // compact alpha x1024 hi/lo
__device__ __align__(256) __half g_al16[(size_t)BB * LL * LL];
// compaction
__device__ int g_idx[BB][LL];
__device__ int g_midx[BB][LL];
__device__ int g_cpos[BB * LL];
__device__ int g_cnt[BB];

// ---------------- helpers ----------------------------------------------------
__device__ __forceinline__ void split2(float v, __nv_bfloat16& h, __nv_bfloat16& l) {
    h = __float2bfloat16_rn(v);
    l = __float2bfloat16_rn(v - __bfloat162float(h));
}
__device__ __forceinline__ void split2h(float v, __half& h, __half& l) {
    h = __float2half_rn(v);
    l = __float2half_rn(v - __half2float(h));
}
__device__ __forceinline__ void cp16(void* smem, const void* gmem) {
    unsigned s = (unsigned)__cvta_generic_to_shared(smem);
    asm volatile("cp.async.cg.shared.global [%0], [%1], 16;\n" :: "r"(s), "l"(gmem));
}
__device__ __forceinline__ void cp_commit() { asm volatile("cp.async.commit_group;\n"); }
__device__ __forceinline__ void cp_wait0()  { asm volatile("cp.async.wait_group 0;\n"); }
__device__ __forceinline__ void cp_wait1()  { asm volatile("cp.async.wait_group 1;\n"); }

__device__ __forceinline__ void ldsm4(unsigned& r0, unsigned& r1, unsigned& r2, unsigned& r3,
                                      const void* p) {
    unsigned s = (unsigned)__cvta_generic_to_shared(p);
    asm volatile("ldmatrix.sync.aligned.m8n8.x4.shared.b16 {%0,%1,%2,%3}, [%4];\n"
                 : "=r"(r0), "=r"(r1), "=r"(r2), "=r"(r3) : "r"(s));
}
__device__ __forceinline__ void mma16816(float* c, const unsigned* a, const unsigned* b) {
    asm volatile(
        "mma.sync.aligned.m16n8k16.row.col.f32.bf16.bf16.f32 "
        "{%0,%1,%2,%3}, {%4,%5,%6,%7}, {%8,%9}, {%0,%1,%2,%3};\n"
        : "+f"(c[0]), "+f"(c[1]), "+f"(c[2]), "+f"(c[3])
        : "r"(a[0]), "r"(a[1]), "r"(a[2]), "r"(a[3]), "r"(b[0]), "r"(b[1]));
}
__device__ __forceinline__ void mma16816h(float* c, const unsigned* a, const unsigned* b) {
    asm volatile(
        "mma.sync.aligned.m16n8k16.row.col.f32.f16.f16.f32 "
        "{%0,%1,%2,%3}, {%4,%5,%6,%7}, {%8,%9}, {%0,%1,%2,%3};\n"
        : "+f"(c[0]), "+f"(c[1]), "+f"(c[2]), "+f"(c[3])
        : "r"(a[0]), "r"(a[1]), "r"(a[2]), "r"(a[3]), "r"(b[0]), "r"(b[1]));
}

// ---------------- shared tile geometry ----------------------------------------
#define BM 128
#define BN 128
#define BK 32
#define SSTR 40
#define TILE_E (128 * SSTR)

// ============ 3-term bf16 template (proj, scores): 4 tiles, 2 stages ==========
#define STAGE_E (4 * TILE_E)
#define SMEM_BYTES (2 * STAGE_E * 2)

__device__ __forceinline__ void load_stage(__nv_bfloat16* st,
                                           const __nv_bfloat16* Ah, const __nv_bfloat16* Al,
                                           const int* __restrict__ rowoff,
                                           const __nv_bfloat16* Bh, const __nv_bfloat16* Bl, int ldb,
                                           int n0, int kk, int tid) {
    __nv_bfloat16* sAH = st;
    __nv_bfloat16* sAL = st + TILE_E;
    __nv_bfloat16* sBH = st + 2 * TILE_E;
    __nv_bfloat16* sBL = st + 3 * TILE_E;
#pragma unroll
    for (int i = 0; i < 2; ++i) {
        int q = tid + i * 256;
        int r = q >> 2, c = (q & 3) * 8;
        size_t ga = (size_t)rowoff[r] + kk + c;
        size_t gb = (size_t)(n0 + r) * ldb + kk + c;
        cp16(&sAH[r * SSTR + c], &Ah[ga]);
        cp16(&sAL[r * SSTR + c], &Al[ga]);
        cp16(&sBH[r * SSTR + c], &Bh[gb]);
        cp16(&sBL[r * SSTR + c], &Bl[gb]);
    }
    cp_commit();
}

__device__ __forceinline__ void compute_stage(float (&acc)[4][4][4],
                                              const __nv_bfloat16* st,
                                              int wm, int wn, int lane) {
    const __nv_bfloat16* sAH = st;
    const __nv_bfloat16* sAL = st + TILE_E;
    const __nv_bfloat16* sBH = st + 2 * TILE_E;
    const __nv_bfloat16* sBL = st + 3 * TILE_E;
#pragma unroll
    for (int ks = 0; ks < 2; ++ks) {
        const int col = ks * 16 + (lane >> 4) * 8;
        const int arow = wm * 64 + (lane & 15);
        const int brow = wn * 32 + (lane & 15);
        unsigned ah[4][4], al[4][4], bh[4][2], bl[4][2];
#pragma unroll
        for (int mt = 0; mt < 4; ++mt) {
            ldsm4(ah[mt][0], ah[mt][1], ah[mt][2], ah[mt][3], &sAH[(arow + mt * 16) * SSTR + col]);
            ldsm4(al[mt][0], al[mt][1], al[mt][2], al[mt][3], &sAL[(arow + mt * 16) * SSTR + col]);
        }
#pragma unroll
        for (int np = 0; np < 2; ++np) {
            unsigned r0, r1, r2, r3;
            ldsm4(r0, r1, r2, r3, &sBH[(brow + np * 16) * SSTR + col]);
            bh[np * 2 + 0][0] = r0; bh[np * 2 + 1][0] = r1;
            bh[np * 2 + 0][1] = r2; bh[np * 2 + 1][1] = r3;
            ldsm4(r0, r1, r2, r3, &sBL[(brow + np * 16) * SSTR + col]);
            bl[np * 2 + 0][0] = r0; bl[np * 2 + 1][0] = r1;
            bl[np * 2 + 0][1] = r2; bl[np * 2 + 1][1] = r3;
        }
#pragma unroll
        for (int mt = 0; mt < 4; ++mt)
#pragma unroll
            for (int nt = 0; nt < 4; ++nt)
                mma16816(acc[mt][nt], ah[mt], bh[nt]);
#pragma unroll
        for (int mt = 0; mt < 4; ++mt)
#pragma unroll
            for (int nt = 0; nt < 4; ++nt)
                mma16816(acc[mt][nt], ah[mt], bl[nt]);
#pragma unroll
        for (int mt = 0; mt < 4; ++mt)
#pragma unroll
            for (int nt = 0; nt < 4; ++nt)
                mma16816(acc[mt][nt], al[mt], bh[nt]);
    }
}

__device__ __forceinline__ void gemm_main(float (&acc)[4][4][4], __nv_bfloat16* sm,
                                          const __nv_bfloat16* Ah, const __nv_bfloat16* Al,
                                          const int* __restrict__ rowoff,
                                          const __nv_bfloat16* Bh, const __nv_bfloat16* Bl, int ldb,
                                          int K, int n0) {
    const int tid = threadIdx.x;
    const int lane = tid & 31, warp = tid >> 5;
    const int wm = warp & 1, wn = warp >> 1;
    const int S = K / BK;

    load_stage(sm, Ah, Al, rowoff, Bh, Bl, ldb, n0, 0, tid);
    for (int s = 0; s < S; ++s) {
        cp_wait0();
        __syncthreads();
        if (s + 1 < S)
            load_stage(sm + ((s + 1) & 1) * STAGE_E, Ah, Al, rowoff, Bh, Bl, ldb,
                       n0, (s + 1) * BK, tid);
        compute_stage(acc, sm + (s & 1) * STAGE_E, wm, wn, lane);
    }
}

// ============ 2-term fp16 template (enc): 3 tiles, 3 stages ====================
#define STAGE2_E (3 * TILE_E)
#define SMEM2_BYTES (3 * STAGE2_E * 2)

__device__ __forceinline__ void load_stage2(__half* st,
                                            const __half* Ah, const __half* Al,
                                            const int* __restrict__ rowoff,
                                            const __half* B, int ldb,
                                            int n0, int kk, int tid) {
    __half* sAH = st;
    __half* sAL = st + TILE_E;
    __half* sB  = st + 2 * TILE_E;
#pragma unroll
    for (int i = 0; i < 2; ++i) {
        int q = tid + i * 256;
        int r = q >> 2, c = (q & 3) * 8;
        size_t ga = (size_t)rowoff[r] + kk + c;
        size_t gb = (size_t)(n0 + r) * ldb + kk + c;
        cp16(&sAH[r * SSTR + c], &Ah[ga]);
        cp16(&sAL[r * SSTR + c], &Al[ga]);
        cp16(&sB[r * SSTR + c], &B[gb]);
    }
    cp_commit();
}

__device__ __forceinline__ void compute_stage2(float (&acc)[4][4][4],
                                               const __half* st,
                                               int wm, int wn, int lane) {
    const __half* sAH = st;
    const __half* sAL = st + TILE_E;
    const __half* sB  = st + 2 * TILE_E;
#pragma unroll
    for (int ks = 0; ks < 2; ++ks) {
        const int col = ks * 16 + (lane >> 4) * 8;
        const int arow = wm * 64 + (lane & 15);
        const int brow = wn * 32 + (lane & 15);
        unsigned ah[4][4], al[4][4], bb[4][2];
#pragma unroll
        for (int mt = 0; mt < 4; ++mt) {
            ldsm4(ah[mt][0], ah[mt][1], ah[mt][2], ah[mt][3], &sAH[(arow + mt * 16) * SSTR + col]);
            ldsm4(al[mt][0], al[mt][1], al[mt][2], al[mt][3], &sAL[(arow + mt * 16) * SSTR + col]);
        }
#pragma unroll
        for (int np = 0; np < 2; ++np) {
            unsigned r0, r1, r2, r3;
            ldsm4(r0, r1, r2, r3, &sB[(brow + np * 16) * SSTR + col]);
            bb[np * 2 + 0][0] = r0; bb[np * 2 + 1][0] = r1;
            bb[np * 2 + 0][1] = r2; bb[np * 2 + 1][1] = r3;
        }
#pragma unroll
        for (int mt = 0; mt < 4; ++mt)
#pragma unroll
            for (int nt = 0; nt < 4; ++nt)
                mma16816h(acc[mt][nt], ah[mt], bb[nt]);
#pragma unroll
        for (int mt = 0; mt < 4; ++mt)
#pragma unroll
            for (int nt = 0; nt < 4; ++nt)
                mma16816h(acc[mt][nt], al[mt], bb[nt]);
    }
}

__device__ __forceinline__ void gemm2_main(float (&acc)[4][4][4], __half* sm,
                                           const __half* Ah, const __half* Al,
                                           const int* __restrict__ rowoff,
                                           const __half* B, int ldb,
                                           int K, int n0) {
    const int tid = threadIdx.x;
    const int lane = tid & 31, warp = tid >> 5;
    const int wm = warp & 1, wn = warp >> 1;
    const int S = K / BK;

    load_stage2(sm, Ah, Al, rowoff, B, ldb, n0, 0, tid);
    load_stage2(sm + STAGE2_E, Ah, Al, rowoff, B, ldb, n0, BK, tid);
    for (int s = 0; s < S; ++s) {
        if (s + 2 < S) cp_wait1(); else cp_wait0();
        __syncthreads();
        if (s + 2 < S)
            load_stage2(sm + (uint32_t)((s + 2) % 3) * STAGE2_E, Ah, Al, rowoff, B, ldb,
                        n0, (s + 2) * BK, tid);
        compute_stage2(acc, sm + (uint32_t)(s % 3) * STAGE2_E, wm, wn, lane);
    }
}

// ============ 1-term fp16 template (gate): 2 tiles, 3 stages ===================
#define STAGE1_E (2 * TILE_E)
#define SMEM1_BYTES (3 * STAGE1_E * 2)

__device__ __forceinline__ void load_stage1(__half* st,
                                            const __half* A,
                                            const int* __restrict__ rowoff,
                                            const __half* B, int ldb,
                                            int n0, int kk, int tid) {
    __half* sA = st;
    __half* sB = st + TILE_E;
#pragma unroll
    for (int i = 0; i < 2; ++i) {
        int q = tid + i * 256;
        int r = q >> 2, c = (q & 3) * 8;
        size_t ga = (size_t)rowoff[r] + kk + c;
        size_t gb = (size_t)(n0 + r) * ldb + kk + c;
        cp16(&sA[r * SSTR + c], &A[ga]);
        cp16(&sB[r * SSTR + c], &B[gb]);
    }
    cp_commit();
}

__device__ __forceinline__ void compute_stage1(float (&acc)[4][4][4],
                                               const __half* st,
                                               int wm, int wn, int lane) {
    const __half* sA = st;
    const __half* sB = st + TILE_E;
#pragma unroll
    for (int ks = 0; ks < 2; ++ks) {
        const int col = ks * 16 + (lane >> 4) * 8;
        const int arow = wm * 64 + (lane & 15);
        const int brow = wn * 32 + (lane & 15);
        unsigned aa[4][4], bb[4][2];
#pragma unroll
        for (int mt = 0; mt < 4; ++mt)
            ldsm4(aa[mt][0], aa[mt][1], aa[mt][2], aa[mt][3], &sA[(arow + mt * 16) * SSTR + col]);
#pragma unroll
        for (int np = 0; np < 2; ++np) {
            unsigned r0, r1, r2, r3;
            ldsm4(r0, r1, r2, r3, &sB[(brow + np * 16) * SSTR + col]);
            bb[np * 2 + 0][0] = r0; bb[np * 2 + 1][0] = r1;
            bb[np * 2 + 0][1] = r2; bb[np * 2 + 1][1] = r3;
        }
#pragma unroll
        for (int mt = 0; mt < 4; ++mt)
#pragma unroll
            for (int nt = 0; nt < 4; ++nt)
                mma16816h(acc[mt][nt], aa[mt], bb[nt]);
    }
}

__device__ __forceinline__ void gemm1_main(float (&acc)[4][4][4], __half* sm,
                                           const __half* A,
                                           const int* __restrict__ rowoff,
                                           const __half* B, int ldb,
                                           int K, int n0) {
    const int tid = threadIdx.x;
    const int lane = tid & 31, warp = tid >> 5;
    const int wm = warp & 1, wn = warp >> 1;
    const int S = K / BK;

    load_stage1(sm, A, rowoff, B, ldb, n0, 0, tid);
    load_stage1(sm + STAGE1_E, A, rowoff, B, ldb, n0, BK, tid);
    for (int s = 0; s < S; ++s) {
        if (s + 2 < S) cp_wait1(); else cp_wait0();
        __syncthreads();
        if (s + 2 < S)
            load_stage1(sm + (uint32_t)((s + 2) % 3) * STAGE1_E, A, rowoff, B, ldb,
                        n0, (s + 2) * BK, tid);
        compute_stage1(acc, sm + (uint32_t)(s % 3) * STAGE1_E, wm, wn, lane);
    }
}

// ---------------- compaction -----------------------------------------------
__global__ void k_compact(const int* __restrict__ xmask) {
    const int b = blockIdx.x;
    const int t = threadIdx.x;
    __shared__ int sc[1024];
    int m = xmask[b * LL + t];
    sc[t] = m;
    __syncthreads();
    for (int off = 1; off < 1024; off <<= 1) {
        int v = (t >= off) ? sc[t - off] : 0;
        __syncthreads();
        sc[t] += v;
        __syncthreads();
    }
    int pos = sc[t] - m;
    if (m) { g_idx[b][pos] = t; g_cpos[b * LL + t] = pos; }
    else   { g_midx[b][t - sc[t]] = t; g_cpos[b * LL + t] = -1; }
    int c = sc[1023];
    if (t == 0) g_cnt[b] = c;
    if (t >= c)      g_idx[b][t] = 0;
    if (t >= LL - c) g_midx[b][t] = 0;
}

// ---------------- prep kernels -----------------------------------------------
__global__ void k_prep_x(const float* __restrict__ X) {
    __shared__ float tile[32][33];
    const int b = blockIdx.z;
    const int l0 = blockIdx.y * 32, h0 = blockIdx.x * 32;
    const int tx = threadIdx.x, ty = threadIdx.y;
#pragma unroll
    for (int i = 0; i < 4; ++i) {
        int l = l0 + ty + 8 * i;
        float v = X[((size_t)b * LL + l) * HH + h0 + tx];
        tile[ty + 8 * i][tx] = v;
        size_t jo = ((size_t)b * LL + l) * H2 + h0 + tx;
        __nv_bfloat16 hh, ll; split2(v, hh, ll);
        g_jh[jo] = hh; g_jl[jo] = ll;
        g_j16[jo] = __float2half_rn(v);
    }
    __syncthreads();
#pragma unroll
    for (int i = 0; i < 4; ++i) {
        int h = h0 + ty + 8 * i;
        int l = l0 + tx;
        float v = tile[tx][ty + 8 * i];
        int p = g_cpos[b * LL + l];
        if (p >= 0)
            g_xt16[((size_t)b * HH + h) * LL + p] = __float2half_rn(v);
    }
}

__global__ void k_prep_wp(const float* __restrict__ W, const float* __restrict__ bp) {
    __shared__ float tile[32][33];
    const int k0 = blockIdx.y * 32, n0 = blockIdx.x * 32;
    const int tx = threadIdx.x, ty = threadIdx.y;
#pragma unroll
    for (int i = 0; i < 4; ++i)
        tile[ty + 8 * i][tx] = W[(size_t)(k0 + ty + 8 * i) * HF + n0 + tx];
    __syncthreads();
#pragma unroll
    for (int i = 0; i < 4; ++i) {
        int n = n0 + ty + 8 * i;
        int np = ((n & 3) << 9) + (n >> 2);
        float v = tile[tx][ty + 8 * i];
        __nv_bfloat16 hh, ll; split2(v, hh, ll);
        size_t o = (size_t)np * HH + k0 + tx;
        g_wph[o] = hh; g_wpl[o] = ll;
        if (k0 == 0 && tx == 0) g_bpr[np] = bp[n];
    }
}

__global__ void k_prep_wg(const float* __restrict__ W) {
    __shared__ float tile[32][33];
    const int k0 = blockIdx.y * 32, n0 = blockIdx.x * 32;
    const int tx = threadIdx.x, ty = threadIdx.y;
#pragma unroll
    for (int i = 0; i < 4; ++i)
        tile[ty + 8 * i][tx] = W[(size_t)(k0 + ty + 8 * i) * H2 + n0 + tx];
    __syncthreads();
#pragma unroll
    for (int i = 0; i < 4; ++i) {
        int n = n0 + ty + 8 * i;
        float v = tile[tx][ty + 8 * i];
        g_wg16[(size_t)n * H2 + k0 + tx] = __float2half_rn(32.0f * v);
    }
}

// ---------------- GEMM kernels -------------------------------------------------
// proj (compact rows)
__global__ __launch_bounds__(256, 2) void k_gemm_proj() {
    extern __shared__ __nv_bfloat16 sm[];
    __shared__ int s_ro[128];
    const int b = blockIdx.z;
    const int cnt = g_cnt[b];
    const int m0 = blockIdx.y * BM;
    if (m0 >= cnt) return;
    const int n0 = blockIdx.x * BN;
    const int tid = threadIdx.x;
    if (tid < 128) s_ro[tid] = (b * LL + g_idx[b][m0 + tid]) * H2;
    __syncthreads();

    float acc[4][4][4] = {};
    gemm_main(acc, sm, g_jh, g_jl, s_ro, g_wph, g_wpl, HH, HH, n0);

    const int lane = tid & 31, warp = tid >> 5;
    const int wm = warp & 1, wn = warp >> 1;
    const int r = lane >> 2, c = (lane & 3) * 2;
#pragma unroll
    for (int mt = 0; mt < 4; ++mt)
#pragma unroll
        for (int nt = 0; nt < 4; ++nt)
#pragma unroll
            for (int half = 0; half < 2; ++half) {
                int m = m0 + wm * 64 + mt * 16 + r + half * 8;
                int n = n0 + wn * 32 + nt * 8 + c;
                float2 bb = *(const float2*)&g_bpr[n];
                float v0 = fmaxf(acc[mt][nt][half * 2 + 0] + bb.x, 0.f);
                float v1 = fmaxf(acc[mt][nt][half * 2 + 1] + bb.y, 0.f);
                int f = n >> 9, h = n & 511;
                size_t o = (((size_t)(b * FF + f)) * LL + m) * HH + h;
                __nv_bfloat16 h0, l0, h1, l1;
                split2(v0, h0, l0); split2(v1, h1, l1);
                __nv_bfloat162 hv; hv.x = h0; hv.y = h1;
                __nv_bfloat162 lv; lv.x = l0; lv.y = l1;
                *(__nv_bfloat162*)&g_yh[o] = hv;
                *(__nv_bfloat162*)&g_yl[o] = lv;
            }
}

// scores (compact, per-factor): Sf = Yf Yf^T upper tiles + mirror. grid (36, FF, BB)
__global__ __launch_bounds__(256, 2) void k_gemm_scores() {
    extern __shared__ __nv_bfloat16 sm[];
    __shared__ int s_ro[128];
    const int b = blockIdx.z;
    const int f = blockIdx.y;
    const int cnt = g_cnt[b];
    int t = blockIdx.x, bi = 0, rowlen = 8;
    while (t >= rowlen) { t -= rowlen; --rowlen; ++bi; }
    const int bj = bi + t;
    const int m0 = bi * BM, n0 = bj * BN;
    if (m0 >= cnt || n0 >= cnt) return;
    const int tid = threadIdx.x;
    if (tid < 128) s_ro[tid] = (m0 + tid) * HH;
    __syncthreads();

    const __nv_bfloat16* Yh = g_yh + ((size_t)(b * FF + f)) * LL * HH;
    const __nv_bfloat16* Yl = g_yl + ((size_t)(b * FF + f)) * LL * HH;
    float acc[4][4][4] = {};
    gemm_main(acc, sm, Yh, Yl, s_ro, Yh, Yl, HH, HH, n0);

    float* Sb = g_Sf + (size_t)(f * BB + b) * LL * LL;
    const int lane = tid & 31, warp = tid >> 5;
    const int wm = warp & 1, wn = warp >> 1;
    const int r = lane >> 2, c = (lane & 3) * 2;
#pragma unroll
    for (int mt = 0; mt < 4; ++mt)
#pragma unroll
        for (int nt = 0; nt < 4; ++nt)
#pragma unroll
            for (int half = 0; half < 2; ++half) {
                int m = m0 + wm * 64 + mt * 16 + r + half * 8;
                int n = n0 + wn * 32 + nt * 8 + c;
                float v0 = acc[mt][nt][half * 2 + 0];
                float v1 = acc[mt][nt][half * 2 + 1];
                float2 fv; fv.x = v0; fv.y = v1;
                *(float2*)&Sb[(size_t)m * LL + n] = fv;
                if (bi != bj && m < cnt) {
                    if (n < cnt)     Sb[(size_t)n * LL + m] = v0;
                    if (n + 1 < cnt) Sb[(size_t)(n + 1) * LL + m] = v1;
                }
            }
}

// masked softmax (smem-tree reductions, round-13 structure); Kp-bounded alpha writes
__global__ void k_softmax() {
    const int blk = blockIdx.x;
    const int b = blk >> 10, j = blk & 1023;
    const int cnt = g_cnt[b];
    if (j >= cnt) return;
    const int t = threadIdx.x;
    const float* S0 = g_Sf + (size_t)(b * LL + j) * LL;
    const size_t fs = (size_t)BB * LL * LL;
    int Kp = (cnt + 31) & ~31;
    if (Kp < 64) Kp = 64;

    float lm[4], msk[4];
    float mx = -CUDART_INF_F;
#pragma unroll
    for (int jj = 0; jj < 4; ++jj) {
        int m = t + jj * 256;
        float v = 0.f, mk = 0.f;
        if (m < cnt) {
            v = S0[m];
            v = fmaxf(v, S0[fs + m]);
            v = fmaxf(v, S0[2 * fs + m]);
            v = fmaxf(v, S0[3 * fs + m]);
            mk = (m != j) ? 1.0f : 0.0f;
            v *= mk;
        }
        lm[jj] = v; msk[jj] = mk;
        mx = fmaxf(mx, v);
    }
    __shared__ float sh[256];
    __shared__ float2 sh2[256];
    sh[t] = mx; __syncthreads();
    for (int s = 128; s > 0; s >>= 1) {
        if (t < s) sh[t] = fmaxf(sh[t], sh[t + s]);
        __syncthreads();
    }
    const float rowmax = sh[0];
    __syncthreads();

    float e[4], z = 0.f, smv = 0.f;
#pragma unroll
    for (int jj = 0; jj < 4; ++jj) {
        e[jj] = __expf(lm[jj] - rowmax);
        z += e[jj];
        smv += e[jj] * msk[jj];
    }
    float2 zz; zz.x = z; zz.y = smv;
    sh2[t] = zz; __syncthreads();
    for (int s = 128; s > 0; s >>= 1) {
        if (t < s) {
            float2 a = sh2[t], bq = sh2[t + s];
            a.x += bq.x; a.y += bq.y;
            sh2[t] = a;
        }
        __syncthreads();
    }
    const float Z  = sh2[0].x;
    const float SM = sh2[0].y;

    const float inv = 1024.0f / (SM + 1e-13f * Z);
#pragma unroll
    for (int jj = 0; jj < 4; ++jj) {
        int m = t + jj * 256;
        if (m >= Kp) continue;
        float a = e[jj] * msk[jj] * inv;
        __half hh, ll; split2h(a, hh, ll);
        size_t o = (size_t)(b * LL + j) * LL + m;
        g_ah16[o] = hh; g_al16[o] = ll;
    }
}

// enc (compact, 2-term fp16)
__global__ __launch_bounds__(256, 2) void k_gemm_enc() {
    extern __shared__ __half sm2[];
    __shared__ int s_ro[128];
    const int b = blockIdx.z;
    const int cnt = g_cnt[b];
    const int m0 = blockIdx.y * BM;
    if (m0 >= cnt) return;
    const int n0 = blockIdx.x * BN;
    const int tid = threadIdx.x;
    if (tid < 128) s_ro[tid] = (m0 + tid) * LL;
    __syncthreads();
    int Kp = (cnt + 31) & ~31;
    if (Kp < 64) Kp = 64;

    float acc[4][4][4] = {};
    gemm2_main(acc, sm2, g_ah16 + (size_t)b * LL * LL, g_al16 + (size_t)b * LL * LL, s_ro,
               g_xt16 + (size_t)b * HH * LL, LL, Kp, n0);

    const int lane = tid & 31, warp = tid >> 5;
    const int wm = warp & 1, wn = warp >> 1;
    const int r = lane >> 2, c = (lane & 3) * 2;
    const float sc = 1.0f / 1024.0f;
#pragma unroll
    for (int mt = 0; mt < 4; ++mt)
#pragma unroll
        for (int nt = 0; nt < 4; ++nt)
#pragma unroll
            for (int half = 0; half < 2; ++half) {
                int j = m0 + wm * 64 + mt * 16 + r + half * 8;
                if (j >= cnt) continue;
                int l = g_idx[b][j];
                int n = n0 + wn * 32 + nt * 8 + c;
                float v0 = acc[mt][nt][half * 2 + 0] * sc;
                float v1 = acc[mt][nt][half * 2 + 1] * sc;
                size_t o = ((size_t)b * LL + l) * H2 + HH + n;
                float2 fv; fv.x = v0; fv.y = v1;
                *(float2*)&g_joint[o] = fv;
                __half2 hv; hv.x = __float2half_rn(v0); hv.y = __float2half_rn(v1);
                *(__half2*)&g_j16[o] = hv;
            }
}

// gate (1-term fp16, row-partitioned): z<8 = active rows (K=1024), z>=8 = masked (K=512)
__global__ __launch_bounds__(256, 2) void k_gemm_gate(const float* __restrict__ X,
                                                      const float* __restrict__ bg,
                                                      float* __restrict__ out) {
    extern __shared__ __half sm1[];
    __shared__ int s_ro[128];
    __shared__ int s_l[128];
    const int z = blockIdx.z;
    const int b = z & 7;
    const bool act = z < 8;
    const int cnt = g_cnt[b];
    const int count = act ? cnt : (LL - cnt);
    const int m0 = blockIdx.y * BM;
    if (m0 >= count) return;
    const int Kdim = act ? H2 : HH;
    const int n0 = blockIdx.x * BN;
    const bool xhalf = (n0 < HH);
    const int tid = threadIdx.x;
    if (tid < 128) {
        int l = act ? g_idx[b][m0 + tid] : g_midx[b][m0 + tid];
        s_l[tid] = l;
        s_ro[tid] = (b * LL + l) * H2;
    }
    __syncthreads();

    float acc[4][4][4] = {};
    gemm1_main(acc, sm1, g_j16, s_ro, g_wg16, H2, Kdim, n0);

    const int lane = tid & 31, warp = tid >> 5;
    const int wm = warp & 1, wn = warp >> 1;
    const int r = lane >> 2, c = (lane & 3) * 2;
    const float sc = 1.0f / 32.0f;
#pragma unroll
    for (int mt = 0; mt < 4; ++mt)
#pragma unroll
        for (int nt = 0; nt < 4; ++nt)
#pragma unroll
            for (int half = 0; half < 2; ++half) {
                int jrow = wm * 64 + mt * 16 + r + half * 8;
                if (m0 + jrow >= count) continue;
                int l = s_l[jrow];
                int n = n0 + wn * 32 + nt * 8 + c;
                float2 bb = *(const float2*)&bg[n];
                float p0 = acc[mt][nt][half * 2 + 0] * sc + bb.x;
                float p1 = acc[mt][nt][half * 2 + 1] * sc + bb.y;
                float g0 = 1.0f / (1.0f + __expf(-p0));
                float g1 = 1.0f / (1.0f + __expf(-p1));
                size_t o = ((size_t)b * LL + l) * H2 + n;
                float2 jv;
                if (xhalf)       jv = *(const float2*)&X[((size_t)b * LL + l) * HH + n];
                else if (act)    jv = *(const float2*)&g_joint[o];
                else           { jv.x = 0.f; jv.y = 0.f; }
                float2 ov; ov.x = g0 * jv.x; ov.y = g1 * jv.y;
                *(float2*)&out[o] = ov;
            }
}

// ---------------- launch --------------------------------------------------------
extern "C" void kernel_launch(void* const* d_in, const int* in_sizes, int n_in,
                              void* d_out, int out_size) {
    const float* x  = (const float*)d_in[0];
    const int*   xm = (const int*)d_in[1];
    const float* Wp = (const float*)d_in[2];
    const float* bp = (const float*)d_in[3];
    const float* Wg = (const float*)d_in[4];
    const float* bg = (const float*)d_in[5];
    float* out = (float*)d_out;

    cudaFuncSetAttribute(k_gemm_proj,   cudaFuncAttributeMaxDynamicSharedMemorySize, SMEM_BYTES);
    cudaFuncSetAttribute(k_gemm_scores, cudaFuncAttributeMaxDynamicSharedMemorySize, SMEM_BYTES);
    cudaFuncSetAttribute(k_gemm_enc,    cudaFuncAttributeMaxDynamicSharedMemorySize, SMEM2_BYTES);
    cudaFuncSetAttribute(k_gemm_gate,   cudaFuncAttributeMaxDynamicSharedMemorySize, SMEM1_BYTES);

    k_compact<<<BB, 1024>>>(xm);

    dim3 tpre(32, 8);
    k_prep_x <<<dim3(HH / 32, LL / 32, BB), tpre>>>(x);
    k_prep_wp<<<dim3(HF / 32, HH / 32), tpre>>>(Wp, bp);
    k_prep_wg<<<dim3(H2 / 32, H2 / 32), tpre>>>(Wg);

    k_gemm_proj  <<<dim3(HF / BN, 8, BB), 256, SMEM_BYTES>>>();
    k_gemm_scores<<<dim3(36, FF, BB), 256, SMEM_BYTES>>>();
    k_softmax    <<<BB * LL, 256>>>();
    k_gemm_enc   <<<dim3(HH / BN, 8, BB), 256, SMEM2_BYTES>>>();
    k_gemm_gate  <<<dim3(H2 / BN, 8, 2 * BB), 256, SMEM1_BYTES>>>(x, bg, out);
}